// round 1
// baseline (speedup 1.0000x reference)
#include <cuda_runtime.h>

#define NUM_HEAD 12
#define BATCH    16
#define SEQ      1024
#define DHEAD    64
#define EMB      768
#define QKVN     2304   // 3 * 12 * 64

// ---------------- scratch (device globals: allocation-free) ----------------
__device__ float g_W[EMB * QKVN];                      //   7 MB packed QKV weights [e][c]
__device__ float g_q[NUM_HEAD * BATCH * DHEAD * SEQ];  //  50 MB  [h][b][d][n]  (d-major!)
__device__ float g_k[NUM_HEAD * BATCH * DHEAD * SEQ];  //  50 MB  [h][b][d][n]
__device__ float g_v[NUM_HEAD * BATCH * SEQ * DHEAD];  //  50 MB  [h][b][n][d]
__device__ float g_o[BATCH * SEQ * EMB];               //  50 MB  [b][n][h*d]

// ---------------- pack U_qkv [h,3,e,d] -> W [e][h*192 + r*64 + d] ----------
__global__ void pack_w_kernel(const float* __restrict__ U) {
    int idx = blockIdx.x * blockDim.x + threadIdx.x;
    if (idx >= EMB * QKVN) return;
    int e = idx / QKVN;
    int c = idx - e * QKVN;
    int h = c / 192;
    int rem = c - h * 192;
    int r = rem >> 6;
    int d = rem & 63;
    g_W[idx] = U[((h * 3 + r) * EMB + e) * DHEAD + d];
}

// ---------------- 128x128x8 fp32 GEMM, 256 threads, 8x8 fragments ----------
// C[M x NC] = A[M x 768] * B[768 x NC]
// MODE 1: A = param (z),  B = g_W,   epilogue scatters to g_q/g_k/g_v
// MODE 2: A = g_o,        B = param, epilogue plain-stores to Cp
template <int NC, int MODE>
__global__ void __launch_bounds__(256) sgemm_kernel(const float* __restrict__ Ap,
                                                    const float* __restrict__ Bp,
                                                    float* __restrict__ Cp) {
    __shared__ float As[8][132];   // A tile transposed: As[k][row]
    __shared__ float Bs[8][132];   // B tile:           Bs[k][col]

    const float* A = (MODE == 2) ? (const float*)g_o : Ap;
    const float* B = (MODE == 1) ? (const float*)g_W : Bp;

    const int t  = threadIdx.x;
    const int m0 = blockIdx.y * 128;
    const int n0 = blockIdx.x * 128;
    const int ty = t >> 4;          // 0..15  -> rows ty*8..ty*8+7
    const int tx = t & 15;          // 0..15  -> cols tx*8..tx*8+7
    const int ar = t >> 1, ac = (t & 1) << 2;   // A-tile loader: row ar, 4 cols at ac
    const int br = t >> 5, bc = (t & 31) << 2;  // B-tile loader: row br, 4 cols at bc

    float acc[8][8];
#pragma unroll
    for (int i = 0; i < 8; i++)
#pragma unroll
        for (int j = 0; j < 8; j++) acc[i][j] = 0.0f;

    const float* Aptr = A + (m0 + ar) * 768 + ac;
    const float* Bptr = B + br * NC + n0 + bc;

    for (int kk = 0; kk < 768; kk += 8) {
        float4 av = *(const float4*)(Aptr + kk);
        float4 bv = *(const float4*)(Bptr + kk * NC);
        __syncthreads();
        As[ac + 0][ar] = av.x;
        As[ac + 1][ar] = av.y;
        As[ac + 2][ar] = av.z;
        As[ac + 3][ar] = av.w;
        *(float4*)&Bs[br][bc] = bv;
        __syncthreads();
#pragma unroll
        for (int k = 0; k < 8; k++) {
            float a0[8], b0[8];
            *(float4*)&a0[0] = *(const float4*)&As[k][ty * 8];
            *(float4*)&a0[4] = *(const float4*)&As[k][ty * 8 + 4];
            *(float4*)&b0[0] = *(const float4*)&Bs[k][tx * 8];
            *(float4*)&b0[4] = *(const float4*)&Bs[k][tx * 8 + 4];
#pragma unroll
            for (int i = 0; i < 8; i++)
#pragma unroll
                for (int j = 0; j < 8; j++) acc[i][j] = fmaf(a0[i], b0[j], acc[i][j]);
        }
    }

    if (MODE == 2) {
#pragma unroll
        for (int i = 0; i < 8; i++) {
            int m = m0 + ty * 8 + i;
            float* dst = Cp + m * NC + n0 + tx * 8;
            *(float4*)dst       = make_float4(acc[i][0], acc[i][1], acc[i][2], acc[i][3]);
            *(float4*)(dst + 4) = make_float4(acc[i][4], acc[i][5], acc[i][6], acc[i][7]);
        }
    } else {
        // column block -> (h, r, d0); one (h,r) group per thread (8 cols stay inside a 64-block)
        const int c0 = n0 + tx * 8;
        const int g  = c0 >> 6;          // h*3 + r
        const int h  = g / 3;
        const int r  = g - h * 3;
        const int d0 = c0 & 63;
#pragma unroll
        for (int i = 0; i < 8; i++) {
            int m = m0 + ty * 8 + i;
            int b = m >> 10;
            int n = m & 1023;
            if (r == 2) {
                // V: [h][b][n][d] (natural)
                float* dst = g_v + ((h * BATCH + b) * SEQ + n) * DHEAD + d0;
                *(float4*)dst       = make_float4(acc[i][0], acc[i][1], acc[i][2], acc[i][3]);
                *(float4*)(dst + 4) = make_float4(acc[i][4], acc[i][5], acc[i][6], acc[i][7]);
            } else {
                // Q/K: [h][b][d][n] (d-major, so flash needs no transpose)
                float* dst = (r == 0 ? g_q : g_k) + ((h * BATCH + b) * DHEAD + d0) * SEQ + n;
#pragma unroll
                for (int j = 0; j < 8; j++) dst[j * SEQ] = acc[i][j];
            }
        }
    }
}

// ---------------- flash attention: 64 q-rows x 64 k-cols per block ---------
// 128 threads: ty = t/8 (16 row-groups of 4), tx = t%8 (8 col-groups of 8)
#define FLASH_SMEM (64 * (68 + 72 + 64 + 68) * 4)

__global__ void __launch_bounds__(128) flash_kernel() {
    extern __shared__ float sm[];
    float(*Qst)[68] = (float(*)[68])sm;                                  // [d][i], pre-scaled
    float(*Kst)[72] = (float(*)[72])(sm + 64 * 68);                      // [d][j]
    float(*Vs)[64]  = (float(*)[64])(sm + 64 * 68 + 64 * 72);            // [j][d]
    float(*Ps)[68]  = (float(*)[68])(sm + 64 * 68 + 64 * 72 + 64 * 64);  // [j][i]

    const int h  = blockIdx.z;
    const int b  = blockIdx.y;
    const int q0 = blockIdx.x * 64;
    const int t  = threadIdx.x;
    const int ty = t >> 3;  // 0..15
    const int tx = t & 7;   // 0..7

    const float SC = 0.125f * 1.4426950408889634f;  // (1/sqrt(64)) * log2(e)

    const float* Qg = g_q + ((h * BATCH + b) * DHEAD) * SEQ + q0;  // row d: +d*SEQ
    const float* Kg = g_k + ((h * BATCH + b) * DHEAD) * SEQ;
    const float* Vg = g_v + ((h * BATCH + b) * SEQ) * DHEAD;

    // load Q tile [d][i] (already d-major in gmem), fold softmax scale in
    for (int idx = t; idx < 64 * 16; idx += 128) {
        int d  = idx >> 4;
        int c4 = (idx & 15) * 4;
        float4 qv = *(const float4*)(Qg + d * SEQ + c4);
        qv.x *= SC; qv.y *= SC; qv.z *= SC; qv.w *= SC;
        *(float4*)&Qst[d][c4] = qv;
    }

    float m_[4], l_[4], o_[4][8];
#pragma unroll
    for (int i = 0; i < 4; i++) {
        m_[i] = -1e30f;
        l_[i] = 0.0f;
#pragma unroll
        for (int j = 0; j < 8; j++) o_[i][j] = 0.0f;
    }

    for (int kt = 0; kt < 16; kt++) {
        __syncthreads();  // prev PV done (Vs/Ps free); also covers initial Q load
        for (int idx = t; idx < 64 * 16; idx += 128) {
            int r  = idx >> 4;
            int c4 = (idx & 15) * 4;
            *(float4*)&Kst[r][c4] = *(const float4*)(Kg + r * SEQ + kt * 64 + c4);  // [d][j]
            *(float4*)&Vs[r][c4]  = *(const float4*)(Vg + (kt * 64 + r) * DHEAD + c4);
        }
        __syncthreads();

        // S = Q K^T  (rank-1 updates over d)
        float s[4][8];
#pragma unroll
        for (int i = 0; i < 4; i++)
#pragma unroll
            for (int j = 0; j < 8; j++) s[i][j] = 0.0f;
#pragma unroll 8
        for (int d = 0; d < 64; d++) {
            float a[4], bb[8];
            *(float4*)&a[0]  = *(const float4*)&Qst[d][ty * 4];
            *(float4*)&bb[0] = *(const float4*)&Kst[d][tx * 8];
            *(float4*)&bb[4] = *(const float4*)&Kst[d][tx * 8 + 4];
#pragma unroll
            for (int i = 0; i < 4; i++)
#pragma unroll
                for (int j = 0; j < 8; j++) s[i][j] = fmaf(a[i], bb[j], s[i][j]);
        }

        // online softmax (rows owned by 8-lane tx-groups)
#pragma unroll
        for (int i = 0; i < 4; i++) {
            float mt = s[i][0];
#pragma unroll
            for (int j = 1; j < 8; j++) mt = fmaxf(mt, s[i][j]);
            mt = fmaxf(mt, __shfl_xor_sync(0xffffffffu, mt, 1));
            mt = fmaxf(mt, __shfl_xor_sync(0xffffffffu, mt, 2));
            mt = fmaxf(mt, __shfl_xor_sync(0xffffffffu, mt, 4));
            float mn   = fmaxf(m_[i], mt);
            float corr = exp2f(m_[i] - mn);
            m_[i] = mn;
            float rs = 0.0f;
#pragma unroll
            for (int j = 0; j < 8; j++) {
                float p = exp2f(s[i][j] - mn);
                s[i][j] = p;
                rs += p;
            }
            rs += __shfl_xor_sync(0xffffffffu, rs, 1);
            rs += __shfl_xor_sync(0xffffffffu, rs, 2);
            rs += __shfl_xor_sync(0xffffffffu, rs, 4);
            l_[i] = l_[i] * corr + rs;
#pragma unroll
            for (int j = 0; j < 8; j++) o_[i][j] *= corr;
#pragma unroll
            for (int j = 0; j < 8; j++) Ps[tx * 8 + j][ty * 4 + i] = s[i][j];
        }
        __syncthreads();

        // O += P V  (rank-1 updates over j)
#pragma unroll 8
        for (int j = 0; j < 64; j++) {
            float a[4], vv[8];
            *(float4*)&a[0]  = *(const float4*)&Ps[j][ty * 4];
            *(float4*)&vv[0] = *(const float4*)&Vs[j][tx * 8];
            *(float4*)&vv[4] = *(const float4*)&Vs[j][tx * 8 + 4];
#pragma unroll
            for (int i = 0; i < 4; i++)
#pragma unroll
                for (int k = 0; k < 8; k++) o_[i][k] = fmaf(a[i], vv[k], o_[i][k]);
        }
    }

    // normalize + store to g_o [b][n][h*64 + d]
#pragma unroll
    for (int i = 0; i < 4; i++) {
        float inv = 1.0f / l_[i];
        int n = q0 + ty * 4 + i;
        float* dst = g_o + (b * SEQ + n) * EMB + h * DHEAD + tx * 8;
        *(float4*)dst = make_float4(o_[i][0] * inv, o_[i][1] * inv, o_[i][2] * inv, o_[i][3] * inv);
        *(float4*)(dst + 4) =
            make_float4(o_[i][4] * inv, o_[i][5] * inv, o_[i][6] * inv, o_[i][7] * inv);
    }
}

// ---------------- launch ---------------------------------------------------
extern "C" void kernel_launch(void* const* d_in, const int* in_sizes, int n_in,
                              void* d_out, int out_size) {
    const float* z    = (const float*)d_in[0];
    const float* Uqkv = (const float*)d_in[1];
    const float* Umsa = (const float*)d_in[2];
    float* out        = (float*)d_out;

    cudaFuncSetAttribute(flash_kernel, cudaFuncAttributeMaxDynamicSharedMemorySize, FLASH_SMEM);

    pack_w_kernel<<<(EMB * QKVN + 255) / 256, 256>>>(Uqkv);

    sgemm_kernel<QKVN, 1><<<dim3(QKVN / 128, (BATCH * SEQ) / 128), 256>>>(z, nullptr, nullptr);

    flash_kernel<<<dim3(SEQ / 64, BATCH, NUM_HEAD), 128, FLASH_SMEM>>>();

    sgemm_kernel<EMB, 2><<<dim3(EMB / 128, (BATCH * SEQ) / 128), 256>>>(nullptr, Umsa, out);
}

// round 3
// speedup vs baseline: 1.4014x; 1.4014x over previous
#include <cuda_runtime.h>
#include <cuda_bf16.h>
#include <cstdint>

#define NUM_HEAD 12
#define BATCH    16
#define SEQ      1024
#define DHEAD    64
#define EMB      768
#define QKVN     2304   // 3 * 12 * 64

// ======================= scratch (device globals) ==========================
__device__ float g_q[NUM_HEAD * BATCH * DHEAD * SEQ];  // [h][b][d][n] (d-major)
__device__ float g_k[NUM_HEAD * BATCH * DHEAD * SEQ];  // [h][b][d][n]
__device__ float g_v[NUM_HEAD * BATCH * SEQ * DHEAD];  // [h][b][n][d]
__device__ float g_o[BATCH * SEQ * EMB];               // [b][n][h*d]
__device__ __nv_bfloat16 g_Wq_hi[QKVN * EMB];          // QKV weights transposed [c][e]
__device__ __nv_bfloat16 g_Wq_lo[QKVN * EMB];
__device__ __nv_bfloat16 g_Wm_hi[EMB * EMB];           // Umsa transposed [n][e]
__device__ __nv_bfloat16 g_Wm_lo[EMB * EMB];

// ---------------- weight packing: f32 -> transposed bf16 hi/lo -------------
__global__ void pack_qkv_kernel(const float* __restrict__ U) {
    int idx = blockIdx.x * blockDim.x + threadIdx.x;
    if (idx >= QKVN * EMB) return;
    int c = idx / EMB, e = idx - c * EMB;
    int h = c / 192, rem = c - h * 192;
    int r = rem >> 6, d = rem & 63;
    float v = U[((h * 3 + r) * EMB + e) * DHEAD + d];
    __nv_bfloat16 hi = __float2bfloat16(v);
    g_Wq_hi[idx] = hi;
    g_Wq_lo[idx] = __float2bfloat16(v - __bfloat162float(hi));
}
__global__ void pack_msa_kernel(const float* __restrict__ U) {
    int idx = blockIdx.x * blockDim.x + threadIdx.x;
    if (idx >= EMB * EMB) return;
    int n = idx / EMB, e = idx - n * EMB;
    float v = U[e * EMB + n];
    __nv_bfloat16 hi = __float2bfloat16(v);
    g_Wm_hi[idx] = hi;
    g_Wm_lo[idx] = __float2bfloat16(v - __bfloat162float(hi));
}

// ======================= warp-MMA helpers (sm_80+) =========================
__device__ __forceinline__ void ldsm_x4(uint32_t& r0, uint32_t& r1, uint32_t& r2, uint32_t& r3,
                                        uint32_t addr) {
    asm volatile("ldmatrix.sync.aligned.m8n8.x4.shared.b16 {%0,%1,%2,%3}, [%4];"
                 : "=r"(r0), "=r"(r1), "=r"(r2), "=r"(r3)
                 : "r"(addr));
}
__device__ __forceinline__ void mma_bf16(float* c, const uint32_t* a, uint32_t b0, uint32_t b1) {
    asm volatile(
        "mma.sync.aligned.m16n8k16.row.col.f32.bf16.bf16.f32 "
        "{%0,%1,%2,%3}, {%4,%5,%6,%7}, {%8,%9}, {%0,%1,%2,%3};"
        : "+f"(c[0]), "+f"(c[1]), "+f"(c[2]), "+f"(c[3])
        : "r"(a[0]), "r"(a[1]), "r"(a[2]), "r"(a[3]), "r"(b0), "r"(b1));
}

// ============ split-bf16 HMMA GEMM: C[M x NC] = A[M x 768] * B^T ===========
// A fp32 (converted on the fly); B pre-packed bf16 hi/lo rows [NC][768].
// Block tile 128(M) x 64(N), 256 threads, warp tile 32x32, K-chunk 32.
// smem rows stride 40 bf16 (80B): 20 banks/row -> conflict-free ldmatrix.
#define AST 40

template <int NC, int MODE>
__global__ void __launch_bounds__(256, 2) hmma_gemm_kernel(const float* __restrict__ Ap,
                                                           float* __restrict__ Cp) {
    __shared__ __nv_bfloat16 Ah[128 * AST], Al[128 * AST];
    __shared__ __nv_bfloat16 Bh[64 * AST], Bl[64 * AST];

    const int t = threadIdx.x, w = t >> 5, l = t & 31;
    const int n0 = blockIdx.x * 64, m0 = blockIdx.y * 128;
    const int wm = w >> 1, wn = w & 1;

    const float* A = (MODE == 2) ? (const float*)g_o : Ap;
    const __nv_bfloat16* Bhg = (MODE == 1) ? (const __nv_bfloat16*)g_Wq_hi
                                           : (const __nv_bfloat16*)g_Wm_hi;
    const __nv_bfloat16* Blg = (MODE == 1) ? (const __nv_bfloat16*)g_Wq_lo
                                           : (const __nv_bfloat16*)g_Wm_lo;

    float acc[2][4][4];
#pragma unroll
    for (int mt = 0; mt < 2; mt++)
#pragma unroll
        for (int nt = 0; nt < 4; nt++)
#pragma unroll
            for (int r = 0; r < 4; r++) acc[mt][nt][r] = 0.0f;

    const uint32_t ahB = (uint32_t)__cvta_generic_to_shared(Ah);
    const uint32_t alB = (uint32_t)__cvta_generic_to_shared(Al);
    const uint32_t bhB = (uint32_t)__cvta_generic_to_shared(Bh);
    const uint32_t blB = (uint32_t)__cvta_generic_to_shared(Bl);

    // ldmatrix lane address components (element offsets; *2 for bytes)
    const int aRow = wm * 32 + (l & 15);              // + mt*16
    const int aCol = (l >> 4) << 3;                   // + k0
    const int bRow = wn * 32 + (l & 7) + ((l >> 4) << 3);  // + g2*16
    const int bCol = ((l >> 3) & 1) << 3;             // + k0

    const int lrow = t >> 3, lc4 = (t & 7) << 2;      // A loader: idx-dependent below
    const int brow = t >> 2, bc8 = (t & 3) << 3;      // B loader

    for (int kc = 0; kc < 768; kc += 32) {
        __syncthreads();
        // ---- load A tile 128x32 f32 -> bf16 hi/lo (swizzle-free, stride 40)
#pragma unroll
        for (int i = 0; i < 4; i++) {
            int idx = t + i * 256;
            int row = idx >> 3, c4 = (idx & 7) << 2;
            float4 av = *(const float4*)(A + (m0 + row) * 768 + kc + c4);
            __nv_bfloat162 h01 = __floats2bfloat162_rn(av.x, av.y);
            __nv_bfloat162 h23 = __floats2bfloat162_rn(av.z, av.w);
            __nv_bfloat162 l01 = __floats2bfloat162_rn(av.x - __bfloat162float(h01.x),
                                                       av.y - __bfloat162float(h01.y));
            __nv_bfloat162 l23 = __floats2bfloat162_rn(av.z - __bfloat162float(h23.x),
                                                       av.w - __bfloat162float(h23.y));
            int off = row * AST + c4;
            *(uint2*)&Ah[off] = make_uint2(*(uint32_t*)&h01, *(uint32_t*)&h23);
            *(uint2*)&Al[off] = make_uint2(*(uint32_t*)&l01, *(uint32_t*)&l23);
        }
        // ---- load B tiles 64x32 bf16 hi/lo
        *(uint4*)&Bh[brow * AST + bc8] = *(const uint4*)(Bhg + (n0 + brow) * 768 + kc + bc8);
        *(uint4*)&Bl[brow * AST + bc8] = *(const uint4*)(Blg + (n0 + brow) * 768 + kc + bc8);
        __syncthreads();

#pragma unroll
        for (int ks = 0; ks < 2; ks++) {
            const int k0 = ks * 16;
            uint32_t ah[2][4], al[2][4], bh[2][4], bl[2][4];
#pragma unroll
            for (int mt = 0; mt < 2; mt++) {
                uint32_t off = 2u * (uint32_t)((aRow + mt * 16) * AST + k0 + aCol);
                ldsm_x4(ah[mt][0], ah[mt][1], ah[mt][2], ah[mt][3], ahB + off);
                ldsm_x4(al[mt][0], al[mt][1], al[mt][2], al[mt][3], alB + off);
            }
#pragma unroll
            for (int g2 = 0; g2 < 2; g2++) {
                uint32_t off = 2u * (uint32_t)((bRow + g2 * 16) * AST + k0 + bCol);
                ldsm_x4(bh[g2][0], bh[g2][1], bh[g2][2], bh[g2][3], bhB + off);
                ldsm_x4(bl[g2][0], bl[g2][1], bl[g2][2], bl[g2][3], blB + off);
            }
#pragma unroll
            for (int mt = 0; mt < 2; mt++)
#pragma unroll
                for (int nt = 0; nt < 4; nt++) {
                    const int g2 = nt >> 1, p = (nt & 1) * 2;
                    mma_bf16(acc[mt][nt], ah[mt], bh[g2][p], bh[g2][p + 1]);
                    mma_bf16(acc[mt][nt], ah[mt], bl[g2][p], bl[g2][p + 1]);
                    mma_bf16(acc[mt][nt], al[mt], bh[g2][p], bh[g2][p + 1]);
                }
        }
    }

    // ---- epilogue. C frag: c0,c1 -> (row rA, cols c,c+1); c2,c3 -> (rA+8, same)
    const int rBase = m0 + wm * 32 + (l >> 2);
    const int cBase = wn * 32 + 2 * (l & 3);
    if (MODE == 2) {
#pragma unroll
        for (int mt = 0; mt < 2; mt++)
#pragma unroll
            for (int nt = 0; nt < 4; nt++) {
                int rA = rBase + mt * 16;
                int c = n0 + cBase + nt * 8;
                *(float2*)(Cp + rA * NC + c) = make_float2(acc[mt][nt][0], acc[mt][nt][1]);
                *(float2*)(Cp + (rA + 8) * NC + c) = make_float2(acc[mt][nt][2], acc[mt][nt][3]);
            }
    } else {
        const int g = n0 >> 6;  // h*3 + r
        const int h = g / 3, r = g - h * 3;
#pragma unroll
        for (int mt = 0; mt < 2; mt++) {
            int m = rBase + mt * 16;
            int b = m >> 10, tok = m & 1023;
#pragma unroll
            for (int nt = 0; nt < 4; nt++) {
                int d = cBase + nt * 8;
                if (r == 2) {
                    float* dst = g_v + ((h * BATCH + b) * SEQ + tok) * DHEAD + d;
                    *(float2*)dst = make_float2(acc[mt][nt][0], acc[mt][nt][1]);
                    *(float2*)(dst + 8 * DHEAD) = make_float2(acc[mt][nt][2], acc[mt][nt][3]);
                } else {
                    float* dst = (r == 0 ? g_q : g_k) + ((h * BATCH + b) * DHEAD + d) * SEQ + tok;
                    dst[0] = acc[mt][nt][0];
                    dst[SEQ] = acc[mt][nt][1];
                    dst[8] = acc[mt][nt][2];
                    dst[SEQ + 8] = acc[mt][nt][3];
                }
            }
        }
    }
}

// ---------------- flash attention (fp32, known good) -----------------------
#define FLASH_SMEM (64 * (68 + 72 + 64 + 68) * 4)

__global__ void __launch_bounds__(128) flash_kernel() {
    extern __shared__ float smf[];
    float(*Qst)[68] = (float(*)[68])smf;
    float(*Kst)[72] = (float(*)[72])(smf + 64 * 68);
    float(*Vs)[64]  = (float(*)[64])(smf + 64 * 68 + 64 * 72);
    float(*Ps)[68]  = (float(*)[68])(smf + 64 * 68 + 64 * 72 + 64 * 64);

    const int h = blockIdx.z, b = blockIdx.y, q0 = blockIdx.x * 64;
    const int t = threadIdx.x, ty = t >> 3, tx = t & 7;
    const float SC = 0.125f * 1.4426950408889634f;

    const float* Qg = g_q + ((h * BATCH + b) * DHEAD) * SEQ + q0;
    const float* Kg = g_k + ((h * BATCH + b) * DHEAD) * SEQ;
    const float* Vg = g_v + ((h * BATCH + b) * SEQ) * DHEAD;

    for (int idx = t; idx < 64 * 16; idx += 128) {
        int d = idx >> 4, c4 = (idx & 15) * 4;
        float4 qv = *(const float4*)(Qg + d * SEQ + c4);
        qv.x *= SC; qv.y *= SC; qv.z *= SC; qv.w *= SC;
        *(float4*)&Qst[d][c4] = qv;
    }

    float m_[4], l_[4], o_[4][8];
#pragma unroll
    for (int i = 0; i < 4; i++) {
        m_[i] = -1e30f; l_[i] = 0.0f;
#pragma unroll
        for (int j = 0; j < 8; j++) o_[i][j] = 0.0f;
    }

    for (int kt = 0; kt < 16; kt++) {
        __syncthreads();
        for (int idx = t; idx < 64 * 16; idx += 128) {
            int r = idx >> 4, c4 = (idx & 15) * 4;
            *(float4*)&Kst[r][c4] = *(const float4*)(Kg + r * SEQ + kt * 64 + c4);
            *(float4*)&Vs[r][c4]  = *(const float4*)(Vg + (kt * 64 + r) * DHEAD + c4);
        }
        __syncthreads();

        float s[4][8];
#pragma unroll
        for (int i = 0; i < 4; i++)
#pragma unroll
            for (int j = 0; j < 8; j++) s[i][j] = 0.0f;
#pragma unroll 8
        for (int d = 0; d < 64; d++) {
            float a[4], bb[8];
            *(float4*)&a[0]  = *(const float4*)&Qst[d][ty * 4];
            *(float4*)&bb[0] = *(const float4*)&Kst[d][tx * 8];
            *(float4*)&bb[4] = *(const float4*)&Kst[d][tx * 8 + 4];
#pragma unroll
            for (int i = 0; i < 4; i++)
#pragma unroll
                for (int j = 0; j < 8; j++) s[i][j] = fmaf(a[i], bb[j], s[i][j]);
        }

#pragma unroll
        for (int i = 0; i < 4; i++) {
            float mt = s[i][0];
#pragma unroll
            for (int j = 1; j < 8; j++) mt = fmaxf(mt, s[i][j]);
            mt = fmaxf(mt, __shfl_xor_sync(0xffffffffu, mt, 1));
            mt = fmaxf(mt, __shfl_xor_sync(0xffffffffu, mt, 2));
            mt = fmaxf(mt, __shfl_xor_sync(0xffffffffu, mt, 4));
            float mn = fmaxf(m_[i], mt);
            float corr = exp2f(m_[i] - mn);
            m_[i] = mn;
            float rs = 0.0f;
#pragma unroll
            for (int j = 0; j < 8; j++) {
                float p = exp2f(s[i][j] - mn);
                s[i][j] = p;
                rs += p;
            }
            rs += __shfl_xor_sync(0xffffffffu, rs, 1);
            rs += __shfl_xor_sync(0xffffffffu, rs, 2);
            rs += __shfl_xor_sync(0xffffffffu, rs, 4);
            l_[i] = l_[i] * corr + rs;
#pragma unroll
            for (int j = 0; j < 8; j++) o_[i][j] *= corr;
#pragma unroll
            for (int j = 0; j < 8; j++) Ps[tx * 8 + j][ty * 4 + i] = s[i][j];
        }
        __syncthreads();

#pragma unroll 8
        for (int j = 0; j < 64; j++) {
            float a[4], vv[8];
            *(float4*)&a[0]  = *(const float4*)&Ps[j][ty * 4];
            *(float4*)&vv[0] = *(const float4*)&Vs[j][tx * 8];
            *(float4*)&vv[4] = *(const float4*)&Vs[j][tx * 8 + 4];
#pragma unroll
            for (int i = 0; i < 4; i++)
#pragma unroll
                for (int k = 0; k < 8; k++) o_[i][k] = fmaf(a[i], vv[k], o_[i][k]);
        }
    }

#pragma unroll
    for (int i = 0; i < 4; i++) {
        float inv = 1.0f / l_[i];
        int n = q0 + ty * 4 + i;
        float* dst = g_o + (b * SEQ + n) * EMB + h * DHEAD + tx * 8;
        *(float4*)dst = make_float4(o_[i][0] * inv, o_[i][1] * inv, o_[i][2] * inv, o_[i][3] * inv);
        *(float4*)(dst + 4) =
            make_float4(o_[i][4] * inv, o_[i][5] * inv, o_[i][6] * inv, o_[i][7] * inv);
    }
}

// ---------------- launch ---------------------------------------------------
extern "C" void kernel_launch(void* const* d_in, const int* in_sizes, int n_in,
                              void* d_out, int out_size) {
    const float* z    = (const float*)d_in[0];
    const float* Uqkv = (const float*)d_in[1];
    const float* Umsa = (const float*)d_in[2];
    float* out        = (float*)d_out;

    cudaFuncSetAttribute(flash_kernel, cudaFuncAttributeMaxDynamicSharedMemorySize, FLASH_SMEM);

    pack_qkv_kernel<<<(QKVN * EMB + 255) / 256, 256>>>(Uqkv);
    pack_msa_kernel<<<(EMB * EMB + 255) / 256, 256>>>(Umsa);

    hmma_gemm_kernel<QKVN, 1><<<dim3(QKVN / 64, (BATCH * SEQ) / 128), 256>>>(z, nullptr);

    flash_kernel<<<dim3(SEQ / 64, BATCH, NUM_HEAD), 128, FLASH_SMEM>>>();

    hmma_gemm_kernel<EMB, 2><<<dim3(EMB / 64, (BATCH * SEQ) / 128), 256>>>(nullptr, out);
}

// round 5
// speedup vs baseline: 2.9782x; 2.1252x over previous
#include <cuda_runtime.h>
#include <cuda_bf16.h>
#include <cstdint>

#define NUM_HEAD 12
#define BATCH    16
#define SEQ      1024
#define DHEAD    64
#define EMB      768
#define QKVN     2304   // 3 * 12 * 64

// ======================= scratch (device globals) ==========================
__device__ __nv_bfloat16 g_q_hi[NUM_HEAD * BATCH * SEQ * DHEAD];  // [h][b][n][d]
__device__ __nv_bfloat16 g_q_lo[NUM_HEAD * BATCH * SEQ * DHEAD];
__device__ __nv_bfloat16 g_k_hi[NUM_HEAD * BATCH * SEQ * DHEAD];  // [h][b][n][d]
__device__ __nv_bfloat16 g_k_lo[NUM_HEAD * BATCH * SEQ * DHEAD];
__device__ __nv_bfloat16 g_vt_hi[NUM_HEAD * BATCH * DHEAD * SEQ]; // [h][b][d][n]
__device__ __nv_bfloat16 g_vt_lo[NUM_HEAD * BATCH * DHEAD * SEQ];
__device__ float g_o[BATCH * SEQ * EMB];                          // [b][n][h*d]
__device__ __nv_bfloat16 g_Wq_hi[QKVN * EMB];                     // QKV weights T [c][e]
__device__ __nv_bfloat16 g_Wq_lo[QKVN * EMB];
__device__ __nv_bfloat16 g_Wm_hi[EMB * EMB];                      // Umsa T [n][e]
__device__ __nv_bfloat16 g_Wm_lo[EMB * EMB];

// ---------------- weight packing: f32 -> transposed bf16 hi/lo -------------
__global__ void pack_qkv_kernel(const float* __restrict__ U) {
    int idx = blockIdx.x * blockDim.x + threadIdx.x;
    if (idx >= QKVN * EMB) return;
    int c = idx / EMB, e = idx - c * EMB;
    int h = c / 192, rem = c - h * 192;
    int r = rem >> 6, d = rem & 63;
    float v = U[((h * 3 + r) * EMB + e) * DHEAD + d];
    __nv_bfloat16 hi = __float2bfloat16(v);
    g_Wq_hi[idx] = hi;
    g_Wq_lo[idx] = __float2bfloat16(v - __bfloat162float(hi));
}
__global__ void pack_msa_kernel(const float* __restrict__ U) {
    int idx = blockIdx.x * blockDim.x + threadIdx.x;
    if (idx >= EMB * EMB) return;
    int n = idx / EMB, e = idx - n * EMB;
    float v = U[e * EMB + n];
    __nv_bfloat16 hi = __float2bfloat16(v);
    g_Wm_hi[idx] = hi;
    g_Wm_lo[idx] = __float2bfloat16(v - __bfloat162float(hi));
}

// ======================= warp-MMA helpers (sm_80+) =========================
__device__ __forceinline__ void ldsm_x4(uint32_t& r0, uint32_t& r1, uint32_t& r2, uint32_t& r3,
                                        uint32_t addr) {
    asm volatile("ldmatrix.sync.aligned.m8n8.x4.shared.b16 {%0,%1,%2,%3}, [%4];"
                 : "=r"(r0), "=r"(r1), "=r"(r2), "=r"(r3)
                 : "r"(addr));
}
__device__ __forceinline__ void mma_bf16(float* c, const uint32_t* a, uint32_t b0, uint32_t b1) {
    asm volatile(
        "mma.sync.aligned.m16n8k16.row.col.f32.bf16.bf16.f32 "
        "{%0,%1,%2,%3}, {%4,%5,%6,%7}, {%8,%9}, {%0,%1,%2,%3};"
        : "+f"(c[0]), "+f"(c[1]), "+f"(c[2]), "+f"(c[3])
        : "r"(a[0]), "r"(a[1]), "r"(a[2]), "r"(a[3]), "r"(b0), "r"(b1));
}
__device__ __forceinline__ __nv_bfloat162 split_hi(float a, float b, __nv_bfloat162& lo) {
    __nv_bfloat162 hi;
    hi.x = __float2bfloat16(a);
    hi.y = __float2bfloat16(b);
    lo.x = __float2bfloat16(a - __bfloat162float(hi.x));
    lo.y = __float2bfloat16(b - __bfloat162float(hi.y));
    return hi;
}
__device__ __forceinline__ uint32_t pack_split(float a, float b, uint32_t& lo_u) {
    __nv_bfloat162 lo;
    __nv_bfloat162 hi = split_hi(a, b, lo);
    lo_u = *(uint32_t*)&lo;
    return *(uint32_t*)&hi;
}

// ============ split-bf16 HMMA GEMM: C[M x NC] = A[M x 768] * B^T ===========
#define AST 40

template <int NC, int MODE>
__global__ void __launch_bounds__(256, 2) hmma_gemm_kernel(const float* __restrict__ Ap,
                                                           float* __restrict__ Cp) {
    __shared__ __nv_bfloat16 Ah[128 * AST], Al[128 * AST];
    __shared__ __nv_bfloat16 Bh[64 * AST], Bl[64 * AST];

    const int t = threadIdx.x, w = t >> 5, l = t & 31;
    const int n0 = blockIdx.x * 64, m0 = blockIdx.y * 128;
    const int wm = w >> 1, wn = w & 1;

    const float* A = (MODE == 2) ? (const float*)g_o : Ap;
    const __nv_bfloat16* Bhg = (MODE == 1) ? (const __nv_bfloat16*)g_Wq_hi
                                           : (const __nv_bfloat16*)g_Wm_hi;
    const __nv_bfloat16* Blg = (MODE == 1) ? (const __nv_bfloat16*)g_Wq_lo
                                           : (const __nv_bfloat16*)g_Wm_lo;

    float acc[2][4][4];
#pragma unroll
    for (int mt = 0; mt < 2; mt++)
#pragma unroll
        for (int nt = 0; nt < 4; nt++)
#pragma unroll
            for (int r = 0; r < 4; r++) acc[mt][nt][r] = 0.0f;

    const uint32_t ahB = (uint32_t)__cvta_generic_to_shared(Ah);
    const uint32_t alB = (uint32_t)__cvta_generic_to_shared(Al);
    const uint32_t bhB = (uint32_t)__cvta_generic_to_shared(Bh);
    const uint32_t blB = (uint32_t)__cvta_generic_to_shared(Bl);

    const int aRow = wm * 32 + (l & 15);
    const int aCol = (l >> 4) << 3;
    const int bRow = wn * 32 + (l & 7) + ((l >> 4) << 3);
    const int bCol = ((l >> 3) & 1) << 3;
    const int brow = t >> 2, bc8 = (t & 3) << 3;

    for (int kc = 0; kc < 768; kc += 32) {
        __syncthreads();
#pragma unroll
        for (int i = 0; i < 4; i++) {
            int idx = t + i * 256;
            int row = idx >> 3, c4 = (idx & 7) << 2;
            float4 av = *(const float4*)(A + (m0 + row) * 768 + kc + c4);
            __nv_bfloat162 l01, l23;
            __nv_bfloat162 h01 = split_hi(av.x, av.y, l01);
            __nv_bfloat162 h23 = split_hi(av.z, av.w, l23);
            int off = row * AST + c4;
            *(uint2*)&Ah[off] = make_uint2(*(uint32_t*)&h01, *(uint32_t*)&h23);
            *(uint2*)&Al[off] = make_uint2(*(uint32_t*)&l01, *(uint32_t*)&l23);
        }
        *(uint4*)&Bh[brow * AST + bc8] = *(const uint4*)(Bhg + (n0 + brow) * 768 + kc + bc8);
        *(uint4*)&Bl[brow * AST + bc8] = *(const uint4*)(Blg + (n0 + brow) * 768 + kc + bc8);
        __syncthreads();

#pragma unroll
        for (int ks = 0; ks < 2; ks++) {
            const int k0 = ks * 16;
            uint32_t ah[2][4], al[2][4], bh[2][4], bl[2][4];
#pragma unroll
            for (int mt = 0; mt < 2; mt++) {
                uint32_t off = 2u * (uint32_t)((aRow + mt * 16) * AST + k0 + aCol);
                ldsm_x4(ah[mt][0], ah[mt][1], ah[mt][2], ah[mt][3], ahB + off);
                ldsm_x4(al[mt][0], al[mt][1], al[mt][2], al[mt][3], alB + off);
            }
#pragma unroll
            for (int g2 = 0; g2 < 2; g2++) {
                uint32_t off = 2u * (uint32_t)((bRow + g2 * 16) * AST + k0 + bCol);
                ldsm_x4(bh[g2][0], bh[g2][1], bh[g2][2], bh[g2][3], bhB + off);
                ldsm_x4(bl[g2][0], bl[g2][1], bl[g2][2], bl[g2][3], blB + off);
            }
#pragma unroll
            for (int mt = 0; mt < 2; mt++)
#pragma unroll
                for (int nt = 0; nt < 4; nt++) {
                    const int g2 = nt >> 1, p = (nt & 1) * 2;
                    mma_bf16(acc[mt][nt], ah[mt], bh[g2][p], bh[g2][p + 1]);
                    mma_bf16(acc[mt][nt], ah[mt], bl[g2][p], bl[g2][p + 1]);
                    mma_bf16(acc[mt][nt], al[mt], bh[g2][p], bh[g2][p + 1]);
                }
        }
    }

    const int rBase = m0 + wm * 32 + (l >> 2);
    const int cBase = wn * 32 + 2 * (l & 3);
    if (MODE == 2) {
#pragma unroll
        for (int mt = 0; mt < 2; mt++)
#pragma unroll
            for (int nt = 0; nt < 4; nt++) {
                int rA = rBase + mt * 16;
                int c = n0 + cBase + nt * 8;
                *(float2*)(Cp + rA * NC + c) = make_float2(acc[mt][nt][0], acc[mt][nt][1]);
                *(float2*)(Cp + (rA + 8) * NC + c) = make_float2(acc[mt][nt][2], acc[mt][nt][3]);
            }
    } else {
        const int g = n0 >> 6;  // h*3 + r
        const int h = g / 3, r = g - h * 3;
#pragma unroll
        for (int mt = 0; mt < 2; mt++) {
            int m = rBase + mt * 16;
            int b = m >> 10, tok = m & 1023;
            int hb = h * BATCH + b;
#pragma unroll
            for (int nt = 0; nt < 4; nt++) {
                int d = cBase + nt * 8;
                if (r == 2) {
                    long base = ((long)hb * DHEAD) * SEQ;
                    __nv_bfloat16 h0 = __float2bfloat16(acc[mt][nt][0]);
                    __nv_bfloat16 h1 = __float2bfloat16(acc[mt][nt][1]);
                    __nv_bfloat16 h2 = __float2bfloat16(acc[mt][nt][2]);
                    __nv_bfloat16 h3 = __float2bfloat16(acc[mt][nt][3]);
                    g_vt_hi[base + (long)d * SEQ + tok] = h0;
                    g_vt_hi[base + (long)(d + 1) * SEQ + tok] = h1;
                    g_vt_hi[base + (long)d * SEQ + tok + 8] = h2;
                    g_vt_hi[base + (long)(d + 1) * SEQ + tok + 8] = h3;
                    g_vt_lo[base + (long)d * SEQ + tok] =
                        __float2bfloat16(acc[mt][nt][0] - __bfloat162float(h0));
                    g_vt_lo[base + (long)(d + 1) * SEQ + tok] =
                        __float2bfloat16(acc[mt][nt][1] - __bfloat162float(h1));
                    g_vt_lo[base + (long)d * SEQ + tok + 8] =
                        __float2bfloat16(acc[mt][nt][2] - __bfloat162float(h2));
                    g_vt_lo[base + (long)(d + 1) * SEQ + tok + 8] =
                        __float2bfloat16(acc[mt][nt][3] - __bfloat162float(h3));
                } else {
                    __nv_bfloat16* dh = (r == 0 ? g_q_hi : g_k_hi);
                    __nv_bfloat16* dl = (r == 0 ? g_q_lo : g_k_lo);
                    long i0 = ((long)hb * SEQ + tok) * DHEAD + d;
                    __nv_bfloat162 lo01, lo23;
                    __nv_bfloat162 hi01 = split_hi(acc[mt][nt][0], acc[mt][nt][1], lo01);
                    __nv_bfloat162 hi23 = split_hi(acc[mt][nt][2], acc[mt][nt][3], lo23);
                    *(__nv_bfloat162*)(dh + i0) = hi01;
                    *(__nv_bfloat162*)(dl + i0) = lo01;
                    *(__nv_bfloat162*)(dh + i0 + 8 * DHEAD) = hi23;
                    *(__nv_bfloat162*)(dl + i0 + 8 * DHEAD) = lo23;
                }
            }
        }
    }
}

// ========= flash attention: FA2-style, warp owns 16 q-rows x all keys =======
// 256 threads, 8 warps; q-block 128. Per iter: 64 keys. P stays in registers.
#define FST 72
#define FQ_H 0
#define FQ_L (128 * FST)
#define FK_H (2 * 128 * FST)
#define FK_L (2 * 128 * FST + 64 * FST)
#define FV_H (2 * 128 * FST + 2 * 64 * FST)
#define FV_L (2 * 128 * FST + 3 * 64 * FST)
#define FLASH_ELEMS (2 * 128 * FST + 4 * 64 * FST)
#define FLASH_SMEM (FLASH_ELEMS * 2)

__global__ void __launch_bounds__(256) flash_kernel() {
    extern __shared__ __nv_bfloat16 sm[];
    const int t = threadIdx.x, w = t >> 5, l = t & 31;
    const int h = blockIdx.z, b = blockIdx.y, q0 = blockIdx.x * 128;
    const int hb = h * BATCH + b;
    const float SC = 0.125f * 1.4426950408889634f;

    const __nv_bfloat16* Qh = g_q_hi + ((long)hb * SEQ + q0) * DHEAD;
    const __nv_bfloat16* Ql = g_q_lo + ((long)hb * SEQ + q0) * DHEAD;
    const __nv_bfloat16* Kh = g_k_hi + (long)hb * SEQ * DHEAD;
    const __nv_bfloat16* Kl = g_k_lo + (long)hb * SEQ * DHEAD;
    const __nv_bfloat16* Vh = g_vt_hi + (long)hb * DHEAD * SEQ;
    const __nv_bfloat16* Vl = g_vt_lo + (long)hb * DHEAD * SEQ;

    const uint32_t smB = (uint32_t)__cvta_generic_to_shared(sm);

    // ---- load Q tile (128 x 64) hi/lo
#pragma unroll
    for (int i = 0; i < 4; i++) {
        int idx = t + i * 256;
        int row = idx >> 3, c8 = (idx & 7) << 3;
        *(uint4*)&sm[FQ_H + row * FST + c8] = *(const uint4*)(Qh + row * DHEAD + c8);
        *(uint4*)&sm[FQ_L + row * FST + c8] = *(const uint4*)(Ql + row * DHEAD + c8);
    }

    float m_[2], l_[2], o_[8][4];
    m_[0] = m_[1] = -1e30f;
    l_[0] = l_[1] = 0.0f;
#pragma unroll
    for (int nt = 0; nt < 8; nt++)
#pragma unroll
        for (int r = 0; r < 4; r++) o_[nt][r] = 0.0f;

    const int aRowOff = w * 16 + (l & 15);             // A frag row (16-row warp tile)
    const int aColOff = (l >> 4) << 3;
    const int bRowOff = (l & 7) + ((l >> 4) << 3);     // + g2*16
    const int bColOff = ((l >> 3) & 1) << 3;
    const int lrow = t >> 3, lc8 = (t & 7) << 3;

    for (int kt = 0; kt < 16; kt++) {
        const int kb = kt * 64;
        __syncthreads();
#pragma unroll
        for (int i = 0; i < 2; i++) {
            int row = lrow + i * 32;
            *(uint4*)&sm[FK_H + row * FST + lc8] = *(const uint4*)(Kh + (long)(kb + row) * DHEAD + lc8);
            *(uint4*)&sm[FK_L + row * FST + lc8] = *(const uint4*)(Kl + (long)(kb + row) * DHEAD + lc8);
            *(uint4*)&sm[FV_H + row * FST + lc8] = *(const uint4*)(Vh + (long)row * SEQ + kb + lc8);
            *(uint4*)&sm[FV_L + row * FST + lc8] = *(const uint4*)(Vl + (long)row * SEQ + kb + lc8);
        }
        __syncthreads();

        // ---- S = Q K^T, warp tile 16q x 64k (nt 0..7), 3-term split
        float s[8][4];
#pragma unroll
        for (int nt = 0; nt < 8; nt++)
#pragma unroll
            for (int r = 0; r < 4; r++) s[nt][r] = 0.0f;
#pragma unroll
        for (int ks = 0; ks < 4; ks++) {
            const int k0 = ks * 16;
            uint32_t qh[4], ql[4], kh[4][4], kl[4][4];
            uint32_t offA = 2u * (uint32_t)(aRowOff * FST + k0 + aColOff);
            ldsm_x4(qh[0], qh[1], qh[2], qh[3], smB + (FQ_H * 2) + offA);
            ldsm_x4(ql[0], ql[1], ql[2], ql[3], smB + (FQ_L * 2) + offA);
#pragma unroll
            for (int g2 = 0; g2 < 4; g2++) {
                uint32_t offB = 2u * (uint32_t)((bRowOff + g2 * 16) * FST + k0 + bColOff);
                ldsm_x4(kh[g2][0], kh[g2][1], kh[g2][2], kh[g2][3], smB + (FK_H * 2) + offB);
                ldsm_x4(kl[g2][0], kl[g2][1], kl[g2][2], kl[g2][3], smB + (FK_L * 2) + offB);
            }
#pragma unroll
            for (int nt = 0; nt < 8; nt++) {
                const int g2 = nt >> 1, p = (nt & 1) * 2;
                mma_bf16(s[nt], qh, kh[g2][p], kh[g2][p + 1]);
                mma_bf16(s[nt], qh, kl[g2][p], kl[g2][p + 1]);
                mma_bf16(s[nt], ql, kh[g2][p], kh[g2][p + 1]);
            }
        }

        // ---- scale + online softmax (row = warp-local: full 64 keys in quad)
#pragma unroll
        for (int nt = 0; nt < 8; nt++)
#pragma unroll
            for (int r = 0; r < 4; r++) s[nt][r] *= SC;

#pragma unroll
        for (int hf = 0; hf < 2; hf++) {
            float mx = -1e30f;
#pragma unroll
            for (int nt = 0; nt < 8; nt++)
                mx = fmaxf(mx, fmaxf(s[nt][hf * 2], s[nt][hf * 2 + 1]));
            mx = fmaxf(mx, __shfl_xor_sync(0xffffffffu, mx, 1));
            mx = fmaxf(mx, __shfl_xor_sync(0xffffffffu, mx, 2));
            float mn = fmaxf(m_[hf], mx);
            float corr = exp2f(m_[hf] - mn);
            m_[hf] = mn;
            float rs = 0.0f;
#pragma unroll
            for (int nt = 0; nt < 8; nt++) {
                float p0 = exp2f(s[nt][hf * 2] - mn);
                float p1 = exp2f(s[nt][hf * 2 + 1] - mn);
                s[nt][hf * 2] = p0;
                s[nt][hf * 2 + 1] = p1;
                rs += p0 + p1;
            }
            rs += __shfl_xor_sync(0xffffffffu, rs, 1);
            rs += __shfl_xor_sync(0xffffffffu, rs, 2);
            l_[hf] = l_[hf] * corr + rs;
#pragma unroll
            for (int nt = 0; nt < 8; nt++) {
                o_[nt][hf * 2] *= corr;
                o_[nt][hf * 2 + 1] *= corr;
            }
        }

        // ---- O += P V: P packed from registers (C-frag == A-frag layout)
#pragma unroll
        for (int ks = 0; ks < 4; ks++) {
            uint32_t pa_h[4], pa_l[4];
            pa_h[0] = pack_split(s[2 * ks][0], s[2 * ks][1], pa_l[0]);
            pa_h[1] = pack_split(s[2 * ks][2], s[2 * ks][3], pa_l[1]);
            pa_h[2] = pack_split(s[2 * ks + 1][0], s[2 * ks + 1][1], pa_l[2]);
            pa_h[3] = pack_split(s[2 * ks + 1][2], s[2 * ks + 1][3], pa_l[3]);
            const int k0 = ks * 16;
            uint32_t vh[4][4], vl[4][4];
#pragma unroll
            for (int g2 = 0; g2 < 4; g2++) {
                uint32_t offB = 2u * (uint32_t)((bRowOff + g2 * 16) * FST + k0 + bColOff);
                ldsm_x4(vh[g2][0], vh[g2][1], vh[g2][2], vh[g2][3], smB + (FV_H * 2) + offB);
                ldsm_x4(vl[g2][0], vl[g2][1], vl[g2][2], vl[g2][3], smB + (FV_L * 2) + offB);
            }
#pragma unroll
            for (int nt = 0; nt < 8; nt++) {
                const int g2 = nt >> 1, p = (nt & 1) * 2;
                mma_bf16(o_[nt], pa_h, vh[g2][p], vh[g2][p + 1]);
                mma_bf16(o_[nt], pa_h, vl[g2][p], vl[g2][p + 1]);
                mma_bf16(o_[nt], pa_l, vh[g2][p], vh[g2][p + 1]);
            }
        }
    }

    // ---- normalize + store to g_o [b][n][h*64 + d]
    const float inv0 = 1.0f / l_[0];
    const float inv1 = 1.0f / l_[1];
    const int row = q0 + w * 16 + (l >> 2);
#pragma unroll
    for (int nt = 0; nt < 8; nt++) {
        int col = h * DHEAD + nt * 8 + 2 * (l & 3);
        *(float2*)(g_o + ((long)b * SEQ + row) * EMB + col) =
            make_float2(o_[nt][0] * inv0, o_[nt][1] * inv0);
        *(float2*)(g_o + ((long)b * SEQ + row + 8) * EMB + col) =
            make_float2(o_[nt][2] * inv1, o_[nt][3] * inv1);
    }
}

// ---------------- launch ---------------------------------------------------
extern "C" void kernel_launch(void* const* d_in, const int* in_sizes, int n_in,
                              void* d_out, int out_size) {
    const float* z    = (const float*)d_in[0];
    const float* Uqkv = (const float*)d_in[1];
    const float* Umsa = (const float*)d_in[2];
    float* out        = (float*)d_out;

    cudaFuncSetAttribute(flash_kernel, cudaFuncAttributeMaxDynamicSharedMemorySize, FLASH_SMEM);

    pack_qkv_kernel<<<(QKVN * EMB + 255) / 256, 256>>>(Uqkv);
    pack_msa_kernel<<<(EMB * EMB + 255) / 256, 256>>>(Umsa);

    hmma_gemm_kernel<QKVN, 1><<<dim3(QKVN / 64, (BATCH * SEQ) / 128), 256>>>(z, nullptr);

    flash_kernel<<<dim3(SEQ / 128, BATCH, NUM_HEAD), 256, FLASH_SMEM>>>();

    hmma_gemm_kernel<EMB, 2><<<dim3(EMB / 64, (BATCH * SEQ) / 128), 256>>>(nullptr, out);
}

// round 6
// speedup vs baseline: 3.0124x; 1.0115x over previous
#include <cuda_runtime.h>
#include <cuda_bf16.h>
#include <cstdint>

#define NUM_HEAD 12
#define BATCH    16
#define SEQ      1024
#define DHEAD    64
#define EMB      768
#define QKVN     2304   // 3 * 12 * 64

// ======================= scratch (device globals) ==========================
__device__ __nv_bfloat16 g_q_hi[NUM_HEAD * BATCH * SEQ * DHEAD];  // [h][b][n][d]
__device__ __nv_bfloat16 g_q_lo[NUM_HEAD * BATCH * SEQ * DHEAD];
__device__ __nv_bfloat16 g_k_hi[NUM_HEAD * BATCH * SEQ * DHEAD];  // [h][b][n][d]
__device__ __nv_bfloat16 g_k_lo[NUM_HEAD * BATCH * SEQ * DHEAD];
__device__ __nv_bfloat16 g_vt_hi[NUM_HEAD * BATCH * DHEAD * SEQ]; // [h][b][d][n]
__device__ __nv_bfloat16 g_vt_lo[NUM_HEAD * BATCH * DHEAD * SEQ];
__device__ float g_o[BATCH * SEQ * EMB];                          // [b][n][h*d]
__device__ __nv_bfloat16 g_Wq_hi[QKVN * EMB];                     // QKV weights T [c][e]
__device__ __nv_bfloat16 g_Wq_lo[QKVN * EMB];
__device__ __nv_bfloat16 g_Wm_hi[EMB * EMB];                      // Umsa T [n][e]
__device__ __nv_bfloat16 g_Wm_lo[EMB * EMB];

// ---------------- weight packing: f32 -> transposed bf16 hi/lo -------------
__global__ void pack_qkv_kernel(const float* __restrict__ U) {
    int idx = blockIdx.x * blockDim.x + threadIdx.x;
    if (idx >= QKVN * EMB) return;
    int c = idx / EMB, e = idx - c * EMB;
    int h = c / 192, rem = c - h * 192;
    int r = rem >> 6, d = rem & 63;
    float v = U[((h * 3 + r) * EMB + e) * DHEAD + d];
    __nv_bfloat16 hi = __float2bfloat16(v);
    g_Wq_hi[idx] = hi;
    g_Wq_lo[idx] = __float2bfloat16(v - __bfloat162float(hi));
}
__global__ void pack_msa_kernel(const float* __restrict__ U) {
    int idx = blockIdx.x * blockDim.x + threadIdx.x;
    if (idx >= EMB * EMB) return;
    int n = idx / EMB, e = idx - n * EMB;
    float v = U[e * EMB + n];
    __nv_bfloat16 hi = __float2bfloat16(v);
    g_Wm_hi[idx] = hi;
    g_Wm_lo[idx] = __float2bfloat16(v - __bfloat162float(hi));
}

// ======================= warp-MMA / async helpers ==========================
__device__ __forceinline__ void ldsm_x4(uint32_t& r0, uint32_t& r1, uint32_t& r2, uint32_t& r3,
                                        uint32_t addr) {
    asm volatile("ldmatrix.sync.aligned.m8n8.x4.shared.b16 {%0,%1,%2,%3}, [%4];"
                 : "=r"(r0), "=r"(r1), "=r"(r2), "=r"(r3)
                 : "r"(addr));
}
__device__ __forceinline__ void mma_bf16(float* c, const uint32_t* a, uint32_t b0, uint32_t b1) {
    asm volatile(
        "mma.sync.aligned.m16n8k16.row.col.f32.bf16.bf16.f32 "
        "{%0,%1,%2,%3}, {%4,%5,%6,%7}, {%8,%9}, {%0,%1,%2,%3};"
        : "+f"(c[0]), "+f"(c[1]), "+f"(c[2]), "+f"(c[3])
        : "r"(a[0]), "r"(a[1]), "r"(a[2]), "r"(a[3]), "r"(b0), "r"(b1));
}
__device__ __forceinline__ void cp_async16(uint32_t smem_addr, const void* gptr) {
    asm volatile("cp.async.cg.shared.global [%0], [%1], 16;" :: "r"(smem_addr), "l"(gptr));
}
#define CP_COMMIT() asm volatile("cp.async.commit_group;" ::: "memory")
#define CP_WAIT0()  asm volatile("cp.async.wait_group 0;" ::: "memory")

__device__ __forceinline__ __nv_bfloat162 split_hi(float a, float b, __nv_bfloat162& lo) {
    __nv_bfloat162 hi;
    hi.x = __float2bfloat16(a);
    hi.y = __float2bfloat16(b);
    lo.x = __float2bfloat16(a - __bfloat162float(hi.x));
    lo.y = __float2bfloat16(b - __bfloat162float(hi.y));
    return hi;
}
__device__ __forceinline__ uint32_t pack_split(float a, float b, uint32_t& lo_u) {
    __nv_bfloat162 lo;
    __nv_bfloat162 hi = split_hi(a, b, lo);
    lo_u = *(uint32_t*)&lo;
    return *(uint32_t*)&hi;
}

// ===== split-bf16 HMMA GEMM: C[M x NC] = A[M x 768] * B^T, 128x128 tile ====
// 256 threads, 8 warps (4m x 2n), warp tile 32m x 64n. K-chunk 32, cp.async
// double-buffered pipeline. Row stride 40 elems (80B) -> conflict-free ldsm.
#define AST   40
#define G_AH  0
#define G_AL  (128 * AST)
#define G_BH  (2 * 128 * AST)
#define G_BL  (3 * 128 * AST)
#define G_BUF (4 * 128 * AST)          // 20480 elems per buffer
#define GEMM_SMEM (2 * G_BUF * 2)      // 81920 bytes

template <int NC, int MODE>
__global__ void __launch_bounds__(256) hmma_gemm_kernel(const float* __restrict__ Ap,
                                                        float* __restrict__ Cp) {
    extern __shared__ __nv_bfloat16 gsm[];
    const int t = threadIdx.x, w = t >> 5, l = t & 31;
    const int n0 = blockIdx.x * 128, m0 = blockIdx.y * 128;
    const int wm = w >> 1, wn = w & 1;

    const float* A = (MODE == 2) ? (const float*)g_o : Ap;
    const __nv_bfloat16* Bhg = (MODE == 1) ? (const __nv_bfloat16*)g_Wq_hi
                                           : (const __nv_bfloat16*)g_Wm_hi;
    const __nv_bfloat16* Blg = (MODE == 1) ? (const __nv_bfloat16*)g_Wq_lo
                                           : (const __nv_bfloat16*)g_Wm_lo;

    float acc[2][8][4];
#pragma unroll
    for (int mt = 0; mt < 2; mt++)
#pragma unroll
        for (int nt = 0; nt < 8; nt++)
#pragma unroll
            for (int r = 0; r < 4; r++) acc[mt][nt][r] = 0.0f;

    const uint32_t smB = (uint32_t)__cvta_generic_to_shared(gsm);

    // fragment address components (verified mappings)
    const int aRow = wm * 32 + (l & 15);            // + mt*16
    const int aCol = (l >> 4) << 3;
    const int bRowOff = (l & 7) + ((l >> 4) << 3);  // + wn*64 + g2*16
    const int bCol = ((l >> 3) & 1) << 3;

    // loader indices
    const int arow = t >> 3, ac4 = (t & 7) << 2;    // +32 rows per i (4 iters of 256)
    const int brow = t >> 2, bc8 = (t & 3) << 3;    // +64 rows per i (2 iters of 256)

    float4 aP[4];

    auto ldgA = [&](int kc) {
#pragma unroll
        for (int i = 0; i < 4; i++)
            aP[i] = *(const float4*)(A + (m0 + arow + i * 32) * 768 + kc + ac4);
    };
    auto cpB = [&](int kc, uint32_t bufEl) {
#pragma unroll
        for (int i = 0; i < 2; i++) {
            int row = brow + i * 64;
            uint32_t off = 2u * (uint32_t)(row * AST + bc8);
            cp_async16(smB + 2u * (bufEl + G_BH) + off, Bhg + (n0 + row) * 768 + kc + bc8);
            cp_async16(smB + 2u * (bufEl + G_BL) + off, Blg + (n0 + row) * 768 + kc + bc8);
        }
    };
    auto stsA = [&](uint32_t bufEl) {
#pragma unroll
        for (int i = 0; i < 4; i++) {
            __nv_bfloat162 l01, l23;
            __nv_bfloat162 h01 = split_hi(aP[i].x, aP[i].y, l01);
            __nv_bfloat162 h23 = split_hi(aP[i].z, aP[i].w, l23);
            int off = (arow + i * 32) * AST + ac4;
            *(uint2*)&gsm[bufEl + G_AH + off] = make_uint2(*(uint32_t*)&h01, *(uint32_t*)&h23);
            *(uint2*)&gsm[bufEl + G_AL + off] = make_uint2(*(uint32_t*)&l01, *(uint32_t*)&l23);
        }
    };

    // ---- prologue: chunk 0 into buffer 0
    ldgA(0);
    cpB(0, 0);
    CP_COMMIT();
    stsA(0);
    CP_WAIT0();
    __syncthreads();

    for (int c = 0; c < 24; c++) {
        const uint32_t cur = (uint32_t)(c & 1) * G_BUF;
        const uint32_t nxt = (uint32_t)((c + 1) & 1) * G_BUF;
        if (c < 23) {
            ldgA((c + 1) * 32);
            cpB((c + 1) * 32, nxt);
            CP_COMMIT();
        }

        const uint32_t aHB = smB + 2u * (cur + G_AH), aLB = smB + 2u * (cur + G_AL);
        const uint32_t bHB = smB + 2u * (cur + G_BH), bLB = smB + 2u * (cur + G_BL);
#pragma unroll
        for (int ks = 0; ks < 2; ks++) {
            const int k0 = ks * 16;
            uint32_t ah[2][4], al[2][4], bh[4][4], bl[4][4];
#pragma unroll
            for (int mt = 0; mt < 2; mt++) {
                uint32_t off = 2u * (uint32_t)((aRow + mt * 16) * AST + k0 + aCol);
                ldsm_x4(ah[mt][0], ah[mt][1], ah[mt][2], ah[mt][3], aHB + off);
                ldsm_x4(al[mt][0], al[mt][1], al[mt][2], al[mt][3], aLB + off);
            }
#pragma unroll
            for (int g2 = 0; g2 < 4; g2++) {
                uint32_t off =
                    2u * (uint32_t)((wn * 64 + g2 * 16 + bRowOff) * AST + k0 + bCol);
                ldsm_x4(bh[g2][0], bh[g2][1], bh[g2][2], bh[g2][3], bHB + off);
                ldsm_x4(bl[g2][0], bl[g2][1], bl[g2][2], bl[g2][3], bLB + off);
            }
#pragma unroll
            for (int mt = 0; mt < 2; mt++)
#pragma unroll
                for (int nt = 0; nt < 8; nt++) {
                    const int g2 = nt >> 1, p = (nt & 1) * 2;
                    mma_bf16(acc[mt][nt], ah[mt], bh[g2][p], bh[g2][p + 1]);
                    mma_bf16(acc[mt][nt], ah[mt], bl[g2][p], bl[g2][p + 1]);
                    mma_bf16(acc[mt][nt], al[mt], bh[g2][p], bh[g2][p + 1]);
                }
        }

        if (c < 23) {
            stsA(nxt);
            CP_WAIT0();
        }
        __syncthreads();
    }

    // ---- epilogue
    const int rBase = m0 + wm * 32 + (l >> 2);
    const int cBase = wn * 64 + 2 * (l & 3);
    if (MODE == 2) {
#pragma unroll
        for (int mt = 0; mt < 2; mt++)
#pragma unroll
            for (int nt = 0; nt < 8; nt++) {
                int rA = rBase + mt * 16;
                int c = n0 + cBase + nt * 8;
                *(float2*)(Cp + rA * NC + c) = make_float2(acc[mt][nt][0], acc[mt][nt][1]);
                *(float2*)(Cp + (rA + 8) * NC + c) = make_float2(acc[mt][nt][2], acc[mt][nt][3]);
            }
    } else {
        const int g = (n0 + wn * 64) >> 6;  // h*3 + r
        const int h = g / 3, r = g - h * 3;
#pragma unroll
        for (int mt = 0; mt < 2; mt++) {
            int m = rBase + mt * 16;
            int b = m >> 10, tok = m & 1023;
            int hb = h * BATCH + b;
#pragma unroll
            for (int nt = 0; nt < 8; nt++) {
                int d = 2 * (l & 3) + nt * 8;
                if (r == 2) {
                    long base = ((long)hb * DHEAD) * SEQ;
                    __nv_bfloat16 h0 = __float2bfloat16(acc[mt][nt][0]);
                    __nv_bfloat16 h1 = __float2bfloat16(acc[mt][nt][1]);
                    __nv_bfloat16 h2 = __float2bfloat16(acc[mt][nt][2]);
                    __nv_bfloat16 h3 = __float2bfloat16(acc[mt][nt][3]);
                    g_vt_hi[base + (long)d * SEQ + tok] = h0;
                    g_vt_hi[base + (long)(d + 1) * SEQ + tok] = h1;
                    g_vt_hi[base + (long)d * SEQ + tok + 8] = h2;
                    g_vt_hi[base + (long)(d + 1) * SEQ + tok + 8] = h3;
                    g_vt_lo[base + (long)d * SEQ + tok] =
                        __float2bfloat16(acc[mt][nt][0] - __bfloat162float(h0));
                    g_vt_lo[base + (long)(d + 1) * SEQ + tok] =
                        __float2bfloat16(acc[mt][nt][1] - __bfloat162float(h1));
                    g_vt_lo[base + (long)d * SEQ + tok + 8] =
                        __float2bfloat16(acc[mt][nt][2] - __bfloat162float(h2));
                    g_vt_lo[base + (long)(d + 1) * SEQ + tok + 8] =
                        __float2bfloat16(acc[mt][nt][3] - __bfloat162float(h3));
                } else {
                    __nv_bfloat16* dh = (r == 0 ? g_q_hi : g_k_hi);
                    __nv_bfloat16* dl = (r == 0 ? g_q_lo : g_k_lo);
                    long i0 = ((long)hb * SEQ + tok) * DHEAD + d;
                    __nv_bfloat162 lo01, lo23;
                    __nv_bfloat162 hi01 = split_hi(acc[mt][nt][0], acc[mt][nt][1], lo01);
                    __nv_bfloat162 hi23 = split_hi(acc[mt][nt][2], acc[mt][nt][3], lo23);
                    *(__nv_bfloat162*)(dh + i0) = hi01;
                    *(__nv_bfloat162*)(dl + i0) = lo01;
                    *(__nv_bfloat162*)(dh + i0 + 8 * DHEAD) = hi23;
                    *(__nv_bfloat162*)(dl + i0 + 8 * DHEAD) = lo23;
                }
            }
        }
    }
}

// ========= flash attention: FA2 + cp.async double-buffered K/V =============
#define FST 72
#define FQ_H 0
#define FQ_L (128 * FST)
#define FKV0 (2 * 128 * FST)
#define KV_KL (64 * FST)
#define KV_VH (2 * 64 * FST)
#define KV_VL (3 * 64 * FST)
#define KV_BUF (4 * 64 * FST)
#define FLASH_SMEM ((2 * 128 * FST + 2 * KV_BUF) * 2)   // 110592 bytes

__global__ void __launch_bounds__(256, 2) flash_kernel() {
    extern __shared__ __nv_bfloat16 sm[];
    const int t = threadIdx.x, w = t >> 5, l = t & 31;
    const int h = blockIdx.z, b = blockIdx.y, q0 = blockIdx.x * 128;
    const int hb = h * BATCH + b;
    const float SC = 0.125f * 1.4426950408889634f;

    const __nv_bfloat16* Qh = g_q_hi + ((long)hb * SEQ + q0) * DHEAD;
    const __nv_bfloat16* Ql = g_q_lo + ((long)hb * SEQ + q0) * DHEAD;
    const __nv_bfloat16* Kh = g_k_hi + (long)hb * SEQ * DHEAD;
    const __nv_bfloat16* Kl = g_k_lo + (long)hb * SEQ * DHEAD;
    const __nv_bfloat16* Vh = g_vt_hi + (long)hb * DHEAD * SEQ;
    const __nv_bfloat16* Vl = g_vt_lo + (long)hb * DHEAD * SEQ;

    const uint32_t smB = (uint32_t)__cvta_generic_to_shared(sm);
    const int lrow = t >> 3, lc8 = (t & 7) << 3;

    auto cpKV = [&](int kb, uint32_t bufEl) {
#pragma unroll
        for (int i = 0; i < 2; i++) {
            int row = lrow + i * 32;
            uint32_t off = 2u * (uint32_t)(row * FST + lc8);
            cp_async16(smB + 2u * bufEl + off, Kh + (long)(kb + row) * DHEAD + lc8);
            cp_async16(smB + 2u * (bufEl + KV_KL) + off, Kl + (long)(kb + row) * DHEAD + lc8);
            cp_async16(smB + 2u * (bufEl + KV_VH) + off, Vh + (long)row * SEQ + kb + lc8);
            cp_async16(smB + 2u * (bufEl + KV_VL) + off, Vl + (long)row * SEQ + kb + lc8);
        }
    };

    // ---- prologue: Q tile + first K/V buffer
    cpKV(0, FKV0);
    CP_COMMIT();
#pragma unroll
    for (int i = 0; i < 4; i++) {
        int idx = t + i * 256;
        int row = idx >> 3, c8 = (idx & 7) << 3;
        *(uint4*)&sm[FQ_H + row * FST + c8] = *(const uint4*)(Qh + row * DHEAD + c8);
        *(uint4*)&sm[FQ_L + row * FST + c8] = *(const uint4*)(Ql + row * DHEAD + c8);
    }
    CP_WAIT0();
    __syncthreads();

    float m_[2], l_[2], o_[8][4];
    m_[0] = m_[1] = -1e30f;
    l_[0] = l_[1] = 0.0f;
#pragma unroll
    for (int nt = 0; nt < 8; nt++)
#pragma unroll
        for (int r = 0; r < 4; r++) o_[nt][r] = 0.0f;

    const int aRowOff = w * 16 + (l & 15);
    const int aColOff = (l >> 4) << 3;
    const int bRowOff = (l & 7) + ((l >> 4) << 3);
    const int bColOff = ((l >> 3) & 1) << 3;

    for (int kt = 0; kt < 16; kt++) {
        const uint32_t cur = FKV0 + (uint32_t)(kt & 1) * KV_BUF;
        if (kt < 15) {
            cpKV((kt + 1) * 64, FKV0 + (uint32_t)((kt + 1) & 1) * KV_BUF);
            CP_COMMIT();
        }
        const uint32_t kvB = smB + 2u * cur;

        // ---- S = Q K^T, 3-term split
        float s[8][4];
#pragma unroll
        for (int nt = 0; nt < 8; nt++)
#pragma unroll
            for (int r = 0; r < 4; r++) s[nt][r] = 0.0f;
#pragma unroll
        for (int ks = 0; ks < 4; ks++) {
            const int k0 = ks * 16;
            uint32_t qh[4], ql[4], kh[4][4], kl[4][4];
            uint32_t offA = 2u * (uint32_t)(aRowOff * FST + k0 + aColOff);
            ldsm_x4(qh[0], qh[1], qh[2], qh[3], smB + (FQ_H * 2) + offA);
            ldsm_x4(ql[0], ql[1], ql[2], ql[3], smB + (FQ_L * 2) + offA);
#pragma unroll
            for (int g2 = 0; g2 < 4; g2++) {
                uint32_t offB = 2u * (uint32_t)((bRowOff + g2 * 16) * FST + k0 + bColOff);
                ldsm_x4(kh[g2][0], kh[g2][1], kh[g2][2], kh[g2][3], kvB + offB);
                ldsm_x4(kl[g2][0], kl[g2][1], kl[g2][2], kl[g2][3], kvB + 2u * KV_KL + offB);
            }
#pragma unroll
            for (int nt = 0; nt < 8; nt++) {
                const int g2 = nt >> 1, p = (nt & 1) * 2;
                mma_bf16(s[nt], qh, kh[g2][p], kh[g2][p + 1]);
                mma_bf16(s[nt], qh, kl[g2][p], kl[g2][p + 1]);
                mma_bf16(s[nt], ql, kh[g2][p], kh[g2][p + 1]);
            }
        }

        // ---- scale + online softmax (warp-local rows)
#pragma unroll
        for (int nt = 0; nt < 8; nt++)
#pragma unroll
            for (int r = 0; r < 4; r++) s[nt][r] *= SC;

#pragma unroll
        for (int hf = 0; hf < 2; hf++) {
            float mx = -1e30f;
#pragma unroll
            for (int nt = 0; nt < 8; nt++)
                mx = fmaxf(mx, fmaxf(s[nt][hf * 2], s[nt][hf * 2 + 1]));
            mx = fmaxf(mx, __shfl_xor_sync(0xffffffffu, mx, 1));
            mx = fmaxf(mx, __shfl_xor_sync(0xffffffffu, mx, 2));
            float mn = fmaxf(m_[hf], mx);
            float corr = exp2f(m_[hf] - mn);
            m_[hf] = mn;
            float rs = 0.0f;
#pragma unroll
            for (int nt = 0; nt < 8; nt++) {
                float p0 = exp2f(s[nt][hf * 2] - mn);
                float p1 = exp2f(s[nt][hf * 2 + 1] - mn);
                s[nt][hf * 2] = p0;
                s[nt][hf * 2 + 1] = p1;
                rs += p0 + p1;
            }
            rs += __shfl_xor_sync(0xffffffffu, rs, 1);
            rs += __shfl_xor_sync(0xffffffffu, rs, 2);
            l_[hf] = l_[hf] * corr + rs;
#pragma unroll
            for (int nt = 0; nt < 8; nt++) {
                o_[nt][hf * 2] *= corr;
                o_[nt][hf * 2 + 1] *= corr;
            }
        }

        // ---- O += P V (P packed from registers)
#pragma unroll
        for (int ks = 0; ks < 4; ks++) {
            uint32_t pa_h[4], pa_l[4];
            pa_h[0] = pack_split(s[2 * ks][0], s[2 * ks][1], pa_l[0]);
            pa_h[1] = pack_split(s[2 * ks][2], s[2 * ks][3], pa_l[1]);
            pa_h[2] = pack_split(s[2 * ks + 1][0], s[2 * ks + 1][1], pa_l[2]);
            pa_h[3] = pack_split(s[2 * ks + 1][2], s[2 * ks + 1][3], pa_l[3]);
            const int k0 = ks * 16;
            uint32_t vh[4][4], vl[4][4];
#pragma unroll
            for (int g2 = 0; g2 < 4; g2++) {
                uint32_t offB = 2u * (uint32_t)((bRowOff + g2 * 16) * FST + k0 + bColOff);
                ldsm_x4(vh[g2][0], vh[g2][1], vh[g2][2], vh[g2][3], kvB + 2u * KV_VH + offB);
                ldsm_x4(vl[g2][0], vl[g2][1], vl[g2][2], vl[g2][3], kvB + 2u * KV_VL + offB);
            }
#pragma unroll
            for (int nt = 0; nt < 8; nt++) {
                const int g2 = nt >> 1, p = (nt & 1) * 2;
                mma_bf16(o_[nt], pa_h, vh[g2][p], vh[g2][p + 1]);
                mma_bf16(o_[nt], pa_h, vl[g2][p], vl[g2][p + 1]);
                mma_bf16(o_[nt], pa_l, vh[g2][p], vh[g2][p + 1]);
            }
        }

        if (kt < 15) CP_WAIT0();
        __syncthreads();
    }

    // ---- normalize + store to g_o [b][n][h*64 + d]
    const float inv0 = 1.0f / l_[0];
    const float inv1 = 1.0f / l_[1];
    const int row = q0 + w * 16 + (l >> 2);
#pragma unroll
    for (int nt = 0; nt < 8; nt++) {
        int col = h * DHEAD + nt * 8 + 2 * (l & 3);
        *(float2*)(g_o + ((long)b * SEQ + row) * EMB + col) =
            make_float2(o_[nt][0] * inv0, o_[nt][1] * inv0);
        *(float2*)(g_o + ((long)b * SEQ + row + 8) * EMB + col) =
            make_float2(o_[nt][2] * inv1, o_[nt][3] * inv1);
    }
}

// ---------------- launch ---------------------------------------------------
extern "C" void kernel_launch(void* const* d_in, const int* in_sizes, int n_in,
                              void* d_out, int out_size) {
    const float* z    = (const float*)d_in[0];
    const float* Uqkv = (const float*)d_in[1];
    const float* Umsa = (const float*)d_in[2];
    float* out        = (float*)d_out;

    cudaFuncSetAttribute(flash_kernel, cudaFuncAttributeMaxDynamicSharedMemorySize, FLASH_SMEM);
    cudaFuncSetAttribute(hmma_gemm_kernel<QKVN, 1>,
                         cudaFuncAttributeMaxDynamicSharedMemorySize, GEMM_SMEM);
    cudaFuncSetAttribute(hmma_gemm_kernel<EMB, 2>,
                         cudaFuncAttributeMaxDynamicSharedMemorySize, GEMM_SMEM);

    pack_qkv_kernel<<<(QKVN * EMB + 255) / 256, 256>>>(Uqkv);
    pack_msa_kernel<<<(EMB * EMB + 255) / 256, 256>>>(Umsa);

    hmma_gemm_kernel<QKVN, 1><<<dim3(QKVN / 128, (BATCH * SEQ) / 128), 256, GEMM_SMEM>>>(z, nullptr);

    flash_kernel<<<dim3(SEQ / 128, BATCH, NUM_HEAD), 256, FLASH_SMEM>>>();

    hmma_gemm_kernel<EMB, 2><<<dim3(EMB / 128, (BATCH * SEQ) / 128), 256, GEMM_SMEM>>>(nullptr, out);
}

// round 8
// speedup vs baseline: 3.4221x; 1.1360x over previous
#include <cuda_runtime.h>
#include <cuda_bf16.h>
#include <cstdint>

#define NUM_HEAD 12
#define BATCH    16
#define SEQ      1024
#define DHEAD    64
#define EMB      768
#define QKVN     2304   // 3 * 12 * 64

// ======================= scratch (device globals) ==========================
__device__ __nv_bfloat16 g_q_hi[NUM_HEAD * BATCH * SEQ * DHEAD];  // [h][b][n][d]
__device__ __nv_bfloat16 g_q_lo[NUM_HEAD * BATCH * SEQ * DHEAD];
__device__ __nv_bfloat16 g_k_hi[NUM_HEAD * BATCH * SEQ * DHEAD];  // [h][b][n][d]
__device__ __nv_bfloat16 g_k_lo[NUM_HEAD * BATCH * SEQ * DHEAD];
__device__ __nv_bfloat16 g_v_hi[NUM_HEAD * BATCH * SEQ * DHEAD];  // [h][b][n][d] (natural!)
__device__ __nv_bfloat16 g_v_lo[NUM_HEAD * BATCH * SEQ * DHEAD];
__device__ float g_o[BATCH * SEQ * EMB];                          // [b][n][h*d]
__device__ __nv_bfloat16 g_Wq_hi[QKVN * EMB];                     // QKV weights T [c][e]
__device__ __nv_bfloat16 g_Wq_lo[QKVN * EMB];
__device__ __nv_bfloat16 g_Wm_hi[EMB * EMB];                      // Umsa T [n][e]
__device__ __nv_bfloat16 g_Wm_lo[EMB * EMB];

// ---------------- weight packing: f32 -> transposed bf16 hi/lo -------------
__global__ void pack_qkv_kernel(const float* __restrict__ U) {
    int idx = blockIdx.x * blockDim.x + threadIdx.x;
    if (idx >= QKVN * EMB) return;
    int c = idx / EMB, e = idx - c * EMB;
    int h = c / 192, rem = c - h * 192;
    int r = rem >> 6, d = rem & 63;
    float v = U[((h * 3 + r) * EMB + e) * DHEAD + d];
    __nv_bfloat16 hi = __float2bfloat16(v);
    g_Wq_hi[idx] = hi;
    g_Wq_lo[idx] = __float2bfloat16(v - __bfloat162float(hi));
}
__global__ void pack_msa_kernel(const float* __restrict__ U) {
    int idx = blockIdx.x * blockDim.x + threadIdx.x;
    if (idx >= EMB * EMB) return;
    int n = idx / EMB, e = idx - n * EMB;
    float v = U[e * EMB + n];
    __nv_bfloat16 hi = __float2bfloat16(v);
    g_Wm_hi[idx] = hi;
    g_Wm_lo[idx] = __float2bfloat16(v - __bfloat162float(hi));
}

// ======================= warp-MMA / async helpers ==========================
__device__ __forceinline__ void ldsm_x4(uint32_t& r0, uint32_t& r1, uint32_t& r2, uint32_t& r3,
                                        uint32_t addr) {
    asm volatile("ldmatrix.sync.aligned.m8n8.x4.shared.b16 {%0,%1,%2,%3}, [%4];"
                 : "=r"(r0), "=r"(r1), "=r"(r2), "=r"(r3)
                 : "r"(addr));
}
__device__ __forceinline__ void ldsm_x4_t(uint32_t& r0, uint32_t& r1, uint32_t& r2, uint32_t& r3,
                                          uint32_t addr) {
    asm volatile("ldmatrix.sync.aligned.m8n8.x4.trans.shared.b16 {%0,%1,%2,%3}, [%4];"
                 : "=r"(r0), "=r"(r1), "=r"(r2), "=r"(r3)
                 : "r"(addr));
}
__device__ __forceinline__ void mma_bf16(float* c, const uint32_t* a, uint32_t b0, uint32_t b1) {
    asm volatile(
        "mma.sync.aligned.m16n8k16.row.col.f32.bf16.bf16.f32 "
        "{%0,%1,%2,%3}, {%4,%5,%6,%7}, {%8,%9}, {%0,%1,%2,%3};"
        : "+f"(c[0]), "+f"(c[1]), "+f"(c[2]), "+f"(c[3])
        : "r"(a[0]), "r"(a[1]), "r"(a[2]), "r"(a[3]), "r"(b0), "r"(b1));
}
__device__ __forceinline__ void cp_async16(uint32_t smem_addr, const void* gptr) {
    asm volatile("cp.async.cg.shared.global [%0], [%1], 16;" :: "r"(smem_addr), "l"(gptr));
}
#define CP_COMMIT() asm volatile("cp.async.commit_group;" ::: "memory")
#define CP_WAIT0()  asm volatile("cp.async.wait_group 0;" ::: "memory")

__device__ __forceinline__ __nv_bfloat162 split_hi(float a, float b, __nv_bfloat162& lo) {
    __nv_bfloat162 hi;
    hi.x = __float2bfloat16(a);
    hi.y = __float2bfloat16(b);
    lo.x = __float2bfloat16(a - __bfloat162float(hi.x));
    lo.y = __float2bfloat16(b - __bfloat162float(hi.y));
    return hi;
}
__device__ __forceinline__ uint32_t pack_split(float a, float b, uint32_t& lo_u) {
    __nv_bfloat162 lo;
    __nv_bfloat162 hi = split_hi(a, b, lo);
    lo_u = *(uint32_t*)&lo;
    return *(uint32_t*)&hi;
}

// ===== split-bf16 HMMA GEMM: C[M x NC] = A[M x 768] * B^T, 128x128 tile ====
// 256 threads, 8 warps (4m x 2n), warp tile 32m x 64n. K-chunk 32, cp.async
// double-buffered pipeline, 2 CTAs/SM. Row stride 40 elems -> conflict-free.
#define AST   40
#define G_AH  0
#define G_AL  (128 * AST)
#define G_BH  (2 * 128 * AST)
#define G_BL  (3 * 128 * AST)
#define G_BUF (4 * 128 * AST)          // 20480 elems per buffer
#define GEMM_SMEM (2 * G_BUF * 2)      // 81920 bytes

template <int NC, int MODE>
__global__ void __launch_bounds__(256, 2) hmma_gemm_kernel(const float* __restrict__ Ap,
                                                           float* __restrict__ Cp) {
    extern __shared__ __nv_bfloat16 gsm[];
    const int t = threadIdx.x, w = t >> 5, l = t & 31;
    const int n0 = blockIdx.x * 128, m0 = blockIdx.y * 128;
    const int wm = w >> 1, wn = w & 1;

    const float* A = (MODE == 2) ? (const float*)g_o : Ap;
    const __nv_bfloat16* Bhg = (MODE == 1) ? (const __nv_bfloat16*)g_Wq_hi
                                           : (const __nv_bfloat16*)g_Wm_hi;
    const __nv_bfloat16* Blg = (MODE == 1) ? (const __nv_bfloat16*)g_Wq_lo
                                           : (const __nv_bfloat16*)g_Wm_lo;

    float acc[2][8][4];
#pragma unroll
    for (int mt = 0; mt < 2; mt++)
#pragma unroll
        for (int nt = 0; nt < 8; nt++)
#pragma unroll
            for (int r = 0; r < 4; r++) acc[mt][nt][r] = 0.0f;

    const uint32_t smB = (uint32_t)__cvta_generic_to_shared(gsm);

    const int aRow = wm * 32 + (l & 15);            // + mt*16
    const int aCol = (l >> 4) << 3;
    const int bRowOff = (l & 7) + ((l >> 4) << 3);  // + wn*64 + g2*16
    const int bCol = ((l >> 3) & 1) << 3;

    const int arow = t >> 3, ac4 = (t & 7) << 2;
    const int brow = t >> 2, bc8 = (t & 3) << 3;

    float4 aP[4];

    auto ldgA = [&](int kc) {
#pragma unroll
        for (int i = 0; i < 4; i++)
            aP[i] = *(const float4*)(A + (m0 + arow + i * 32) * 768 + kc + ac4);
    };
    auto cpB = [&](int kc, uint32_t bufEl) {
#pragma unroll
        for (int i = 0; i < 2; i++) {
            int row = brow + i * 64;
            uint32_t off = 2u * (uint32_t)(row * AST + bc8);
            cp_async16(smB + 2u * (bufEl + G_BH) + off, Bhg + (n0 + row) * 768 + kc + bc8);
            cp_async16(smB + 2u * (bufEl + G_BL) + off, Blg + (n0 + row) * 768 + kc + bc8);
        }
    };
    auto stsA = [&](uint32_t bufEl) {
#pragma unroll
        for (int i = 0; i < 4; i++) {
            __nv_bfloat162 l01, l23;
            __nv_bfloat162 h01 = split_hi(aP[i].x, aP[i].y, l01);
            __nv_bfloat162 h23 = split_hi(aP[i].z, aP[i].w, l23);
            int off = (arow + i * 32) * AST + ac4;
            *(uint2*)&gsm[bufEl + G_AH + off] = make_uint2(*(uint32_t*)&h01, *(uint32_t*)&h23);
            *(uint2*)&gsm[bufEl + G_AL + off] = make_uint2(*(uint32_t*)&l01, *(uint32_t*)&l23);
        }
    };

    ldgA(0);
    cpB(0, 0);
    CP_COMMIT();
    stsA(0);
    CP_WAIT0();
    __syncthreads();

    for (int c = 0; c < 24; c++) {
        const uint32_t cur = (uint32_t)(c & 1) * G_BUF;
        const uint32_t nxt = (uint32_t)((c + 1) & 1) * G_BUF;
        if (c < 23) {
            ldgA((c + 1) * 32);
            cpB((c + 1) * 32, nxt);
            CP_COMMIT();
        }

        const uint32_t aHB = smB + 2u * (cur + G_AH), aLB = smB + 2u * (cur + G_AL);
        const uint32_t bHB = smB + 2u * (cur + G_BH), bLB = smB + 2u * (cur + G_BL);
#pragma unroll
        for (int ks = 0; ks < 2; ks++) {
            const int k0 = ks * 16;
            uint32_t ah[2][4], al[2][4], bh[4][4], bl[4][4];
#pragma unroll
            for (int mt = 0; mt < 2; mt++) {
                uint32_t off = 2u * (uint32_t)((aRow + mt * 16) * AST + k0 + aCol);
                ldsm_x4(ah[mt][0], ah[mt][1], ah[mt][2], ah[mt][3], aHB + off);
                ldsm_x4(al[mt][0], al[mt][1], al[mt][2], al[mt][3], aLB + off);
            }
#pragma unroll
            for (int g2 = 0; g2 < 4; g2++) {
                uint32_t off =
                    2u * (uint32_t)((wn * 64 + g2 * 16 + bRowOff) * AST + k0 + bCol);
                ldsm_x4(bh[g2][0], bh[g2][1], bh[g2][2], bh[g2][3], bHB + off);
                ldsm_x4(bl[g2][0], bl[g2][1], bl[g2][2], bl[g2][3], bLB + off);
            }
#pragma unroll
            for (int mt = 0; mt < 2; mt++)
#pragma unroll
                for (int nt = 0; nt < 8; nt++) {
                    const int g2 = nt >> 1, p = (nt & 1) * 2;
                    mma_bf16(acc[mt][nt], ah[mt], bh[g2][p], bh[g2][p + 1]);
                    mma_bf16(acc[mt][nt], ah[mt], bl[g2][p], bl[g2][p + 1]);
                    mma_bf16(acc[mt][nt], al[mt], bh[g2][p], bh[g2][p + 1]);
                }
        }

        if (c < 23) {
            stsA(nxt);
            CP_WAIT0();
        }
        __syncthreads();
    }

    // ---- epilogue
    const int rBase = m0 + wm * 32 + (l >> 2);
    const int cBase = wn * 64 + 2 * (l & 3);
    if (MODE == 2) {
#pragma unroll
        for (int mt = 0; mt < 2; mt++)
#pragma unroll
            for (int nt = 0; nt < 8; nt++) {
                int rA = rBase + mt * 16;
                int c = n0 + cBase + nt * 8;
                *(float2*)(Cp + rA * NC + c) = make_float2(acc[mt][nt][0], acc[mt][nt][1]);
                *(float2*)(Cp + (rA + 8) * NC + c) = make_float2(acc[mt][nt][2], acc[mt][nt][3]);
            }
    } else {
        // QKV epilogue: all of q/k/v in natural [h][b][n][d] bf16 hi/lo
        const int g = (n0 + wn * 64) >> 6;  // h*3 + r
        const int h = g / 3, r = g - h * 3;
        __nv_bfloat16* dh = (r == 0 ? g_q_hi : (r == 1 ? g_k_hi : g_v_hi));
        __nv_bfloat16* dl = (r == 0 ? g_q_lo : (r == 1 ? g_k_lo : g_v_lo));
#pragma unroll
        for (int mt = 0; mt < 2; mt++) {
            int m = rBase + mt * 16;
            int b = m >> 10, tok = m & 1023;
            int hb = h * BATCH + b;
#pragma unroll
            for (int nt = 0; nt < 8; nt++) {
                int d = 2 * (l & 3) + nt * 8;
                long i0 = ((long)hb * SEQ + tok) * DHEAD + d;
                __nv_bfloat162 lo01, lo23;
                __nv_bfloat162 hi01 = split_hi(acc[mt][nt][0], acc[mt][nt][1], lo01);
                __nv_bfloat162 hi23 = split_hi(acc[mt][nt][2], acc[mt][nt][3], lo23);
                *(__nv_bfloat162*)(dh + i0) = hi01;
                *(__nv_bfloat162*)(dl + i0) = lo01;
                *(__nv_bfloat162*)(dh + i0 + 8 * DHEAD) = hi23;
                *(__nv_bfloat162*)(dl + i0 + 8 * DHEAD) = lo23;
            }
        }
    }
}

// ========= flash attention: FA2 + cp.async; V natural via ldsm.trans =======
#define FST 72
#define FQ_H 0
#define FQ_L (128 * FST)
#define FKV0 (2 * 128 * FST)
#define KV_KL (64 * FST)
#define KV_VH (2 * 64 * FST)
#define KV_VL (3 * 64 * FST)
#define KV_BUF (4 * 64 * FST)
#define FLASH_SMEM ((2 * 128 * FST + 2 * KV_BUF) * 2)   // 110592 bytes

__global__ void __launch_bounds__(256, 2) flash_kernel() {
    extern __shared__ __nv_bfloat16 sm[];
    const int t = threadIdx.x, w = t >> 5, l = t & 31;
    const int h = blockIdx.z, b = blockIdx.y, q0 = blockIdx.x * 128;
    const int hb = h * BATCH + b;
    const float SC = 0.125f * 1.4426950408889634f;

    const __nv_bfloat16* Qh = g_q_hi + ((long)hb * SEQ + q0) * DHEAD;
    const __nv_bfloat16* Ql = g_q_lo + ((long)hb * SEQ + q0) * DHEAD;
    const __nv_bfloat16* Kh = g_k_hi + (long)hb * SEQ * DHEAD;
    const __nv_bfloat16* Kl = g_k_lo + (long)hb * SEQ * DHEAD;
    const __nv_bfloat16* Vh = g_v_hi + (long)hb * SEQ * DHEAD;
    const __nv_bfloat16* Vl = g_v_lo + (long)hb * SEQ * DHEAD;

    const uint32_t smB = (uint32_t)__cvta_generic_to_shared(sm);
    const int lrow = t >> 3, lc8 = (t & 7) << 3;

    // K and V both stored [key][d] in smem (V fragments come via ldsm.trans)
    auto cpKV = [&](int kb, uint32_t bufEl) {
#pragma unroll
        for (int i = 0; i < 2; i++) {
            int row = lrow + i * 32;
            uint32_t off = 2u * (uint32_t)(row * FST + lc8);
            cp_async16(smB + 2u * bufEl + off, Kh + (long)(kb + row) * DHEAD + lc8);
            cp_async16(smB + 2u * (bufEl + KV_KL) + off, Kl + (long)(kb + row) * DHEAD + lc8);
            cp_async16(smB + 2u * (bufEl + KV_VH) + off, Vh + (long)(kb + row) * DHEAD + lc8);
            cp_async16(smB + 2u * (bufEl + KV_VL) + off, Vl + (long)(kb + row) * DHEAD + lc8);
        }
    };

    cpKV(0, FKV0);
    CP_COMMIT();
#pragma unroll
    for (int i = 0; i < 4; i++) {
        int idx = t + i * 256;
        int row = idx >> 3, c8 = (idx & 7) << 3;
        *(uint4*)&sm[FQ_H + row * FST + c8] = *(const uint4*)(Qh + row * DHEAD + c8);
        *(uint4*)&sm[FQ_L + row * FST + c8] = *(const uint4*)(Ql + row * DHEAD + c8);
    }
    CP_WAIT0();
    __syncthreads();

    float m_[2], l_[2], o_[8][4];
    m_[0] = m_[1] = -1e30f;
    l_[0] = l_[1] = 0.0f;
#pragma unroll
    for (int nt = 0; nt < 8; nt++)
#pragma unroll
        for (int r = 0; r < 4; r++) o_[nt][r] = 0.0f;

    const int aRowOff = w * 16 + (l & 15);
    const int aColOff = (l >> 4) << 3;
    const int bRowOff = (l & 7) + ((l >> 4) << 3);      // K (non-trans B)
    const int bColOff = ((l >> 3) & 1) << 3;
    const int vRowOff = (l & 7) + (((l >> 3) & 1) << 3);  // V (trans B): row = key
    const int vColOff = (l >> 4) << 3;                    //              col = dv

    for (int kt = 0; kt < 16; kt++) {
        const uint32_t cur = FKV0 + (uint32_t)(kt & 1) * KV_BUF;
        if (kt < 15) {
            cpKV((kt + 1) * 64, FKV0 + (uint32_t)((kt + 1) & 1) * KV_BUF);
            CP_COMMIT();
        }
        const uint32_t kvB = smB + 2u * cur;

        // ---- S = Q K^T, 3-term split
        float s[8][4];
#pragma unroll
        for (int nt = 0; nt < 8; nt++)
#pragma unroll
            for (int r = 0; r < 4; r++) s[nt][r] = 0.0f;
#pragma unroll
        for (int ks = 0; ks < 4; ks++) {
            const int k0 = ks * 16;
            uint32_t qh[4], ql[4], kh[4][4], kl[4][4];
            uint32_t offA = 2u * (uint32_t)(aRowOff * FST + k0 + aColOff);
            ldsm_x4(qh[0], qh[1], qh[2], qh[3], smB + (FQ_H * 2) + offA);
            ldsm_x4(ql[0], ql[1], ql[2], ql[3], smB + (FQ_L * 2) + offA);
#pragma unroll
            for (int g2 = 0; g2 < 4; g2++) {
                uint32_t offB = 2u * (uint32_t)((bRowOff + g2 * 16) * FST + k0 + bColOff);
                ldsm_x4(kh[g2][0], kh[g2][1], kh[g2][2], kh[g2][3], kvB + offB);
                ldsm_x4(kl[g2][0], kl[g2][1], kl[g2][2], kl[g2][3], kvB + 2u * KV_KL + offB);
            }
#pragma unroll
            for (int nt = 0; nt < 8; nt++) {
                const int g2 = nt >> 1, p = (nt & 1) * 2;
                mma_bf16(s[nt], qh, kh[g2][p], kh[g2][p + 1]);
                mma_bf16(s[nt], qh, kl[g2][p], kl[g2][p + 1]);
                mma_bf16(s[nt], ql, kh[g2][p], kh[g2][p + 1]);
            }
        }

        // ---- scale + online softmax (warp-local rows)
#pragma unroll
        for (int nt = 0; nt < 8; nt++)
#pragma unroll
            for (int r = 0; r < 4; r++) s[nt][r] *= SC;

#pragma unroll
        for (int hf = 0; hf < 2; hf++) {
            float mx = -1e30f;
#pragma unroll
            for (int nt = 0; nt < 8; nt++)
                mx = fmaxf(mx, fmaxf(s[nt][hf * 2], s[nt][hf * 2 + 1]));
            mx = fmaxf(mx, __shfl_xor_sync(0xffffffffu, mx, 1));
            mx = fmaxf(mx, __shfl_xor_sync(0xffffffffu, mx, 2));
            float mn = fmaxf(m_[hf], mx);
            float corr = exp2f(m_[hf] - mn);
            m_[hf] = mn;
            float rs = 0.0f;
#pragma unroll
            for (int nt = 0; nt < 8; nt++) {
                float p0 = exp2f(s[nt][hf * 2] - mn);
                float p1 = exp2f(s[nt][hf * 2 + 1] - mn);
                s[nt][hf * 2] = p0;
                s[nt][hf * 2 + 1] = p1;
                rs += p0 + p1;
            }
            rs += __shfl_xor_sync(0xffffffffu, rs, 1);
            rs += __shfl_xor_sync(0xffffffffu, rs, 2);
            l_[hf] = l_[hf] * corr + rs;
#pragma unroll
            for (int nt = 0; nt < 8; nt++) {
                o_[nt][hf * 2] *= corr;
                o_[nt][hf * 2 + 1] *= corr;
            }
        }

        // ---- O += P V (P packed from registers; V fragments via ldsm.trans)
#pragma unroll
        for (int ks = 0; ks < 4; ks++) {
            uint32_t pa_h[4], pa_l[4];
            pa_h[0] = pack_split(s[2 * ks][0], s[2 * ks][1], pa_l[0]);
            pa_h[1] = pack_split(s[2 * ks][2], s[2 * ks][3], pa_l[1]);
            pa_h[2] = pack_split(s[2 * ks + 1][0], s[2 * ks + 1][1], pa_l[2]);
            pa_h[3] = pack_split(s[2 * ks + 1][2], s[2 * ks + 1][3], pa_l[3]);
            const int k0 = ks * 16;  // key base
            uint32_t vh[4][4], vl[4][4];
#pragma unroll
            for (int g2 = 0; g2 < 4; g2++) {  // g2 = dv 16-block
                uint32_t offV =
                    2u * (uint32_t)((k0 + vRowOff) * FST + g2 * 16 + vColOff);
                ldsm_x4_t(vh[g2][0], vh[g2][1], vh[g2][2], vh[g2][3], kvB + 2u * KV_VH + offV);
                ldsm_x4_t(vl[g2][0], vl[g2][1], vl[g2][2], vl[g2][3], kvB + 2u * KV_VL + offV);
            }
#pragma unroll
            for (int nt = 0; nt < 8; nt++) {
                const int g2 = nt >> 1, p = (nt & 1) * 2;
                mma_bf16(o_[nt], pa_h, vh[g2][p], vh[g2][p + 1]);
                mma_bf16(o_[nt], pa_h, vl[g2][p], vl[g2][p + 1]);
                mma_bf16(o_[nt], pa_l, vh[g2][p], vh[g2][p + 1]);
            }
        }

        if (kt < 15) CP_WAIT0();
        __syncthreads();
    }

    // ---- normalize + store to g_o [b][n][h*64 + d]
    const float inv0 = 1.0f / l_[0];
    const float inv1 = 1.0f / l_[1];
    const int row = q0 + w * 16 + (l >> 2);
#pragma unroll
    for (int nt = 0; nt < 8; nt++) {
        int col = h * DHEAD + nt * 8 + 2 * (l & 3);
        *(float2*)(g_o + ((long)b * SEQ + row) * EMB + col) =
            make_float2(o_[nt][0] * inv0, o_[nt][1] * inv0);
        *(float2*)(g_o + ((long)b * SEQ + row + 8) * EMB + col) =
            make_float2(o_[nt][2] * inv1, o_[nt][3] * inv1);
    }
}

// ---------------- launch ---------------------------------------------------
extern "C" void kernel_launch(void* const* d_in, const int* in_sizes, int n_in,
                              void* d_out, int out_size) {
    const float* z    = (const float*)d_in[0];
    const float* Uqkv = (const float*)d_in[1];
    const float* Umsa = (const float*)d_in[2];
    float* out        = (float*)d_out;

    cudaFuncSetAttribute(flash_kernel, cudaFuncAttributeMaxDynamicSharedMemorySize, FLASH_SMEM);
    cudaFuncSetAttribute(hmma_gemm_kernel<QKVN, 1>,
                         cudaFuncAttributeMaxDynamicSharedMemorySize, GEMM_SMEM);
    cudaFuncSetAttribute(hmma_gemm_kernel<EMB, 2>,
                         cudaFuncAttributeMaxDynamicSharedMemorySize, GEMM_SMEM);

    pack_qkv_kernel<<<(QKVN * EMB + 255) / 256, 256>>>(Uqkv);
    pack_msa_kernel<<<(EMB * EMB + 255) / 256, 256>>>(Umsa);

    hmma_gemm_kernel<QKVN, 1><<<dim3(QKVN / 128, (BATCH * SEQ) / 128), 256, GEMM_SMEM>>>(z, nullptr);

    flash_kernel<<<dim3(SEQ / 128, BATCH, NUM_HEAD), 256, FLASH_SMEM>>>();

    hmma_gemm_kernel<EMB, 2><<<dim3(EMB / 128, (BATCH * SEQ) / 128), 256, GEMM_SMEM>>>(nullptr, out);
}